// round 1
// baseline (speedup 1.0000x reference)
#include <cuda_runtime.h>
#include <cuda_bf16.h>
#include <math.h>

// Problem constants
#define BB   16
#define CC   192
#define HH   128
#define WW   128
#define HW   16384          // 128*128
#define C3   576            // 3*C
#define HEADS 4
#define HD   48             // head dim
#define TN   16384          // GEMM N (always HW)

// ---------------------------------------------------------------------------
// Scratch (device globals: allocation-free per harness rules)
// ---------------------------------------------------------------------------
__device__ float g_qkv [(size_t)BB * C3 * HW];   // after 1x1 conv      (~604 MB)
__device__ float g_qkvd[(size_t)BB * C3 * HW];   // after depthwise 3x3 (~604 MB)
__device__ float g_S   [BB * HEADS * HD * HD];   // gram -> attn
__device__ float g_n2  [BB * HEADS * 2 * HD];    // sum-of-squares: q rows [0..48), k rows [48..96)
__device__ float g_M   [BB * CC * CC];           // fused  Wp @ blockdiag(attn)

// ---------------------------------------------------------------------------
// zero helper
// ---------------------------------------------------------------------------
__global__ void zero_kernel(float* a, int n) {
    int i = blockIdx.x * blockDim.x + threadIdx.x;
    if (i < n) a[i] = 0.f;
}

// ---------------------------------------------------------------------------
// Generic batched GEMM: C[M x 16384] = A[M x K] * B[K x 16384]
// 64x64 tile, BK=16, 16x16 threads, 4x4 register blocking, float4 I/O.
// M % 64 == 0, K % 16 == 0 (holds: M in {576,192}, K = 192).
// ---------------------------------------------------------------------------
__global__ __launch_bounds__(256)
void gemm64(const float* __restrict__ A, const float* __restrict__ B,
            float* __restrict__ C, int M, int K,
            size_t strideA, size_t strideB, size_t strideC) {
    int b = blockIdx.z;
    A += (size_t)b * strideA;
    B += (size_t)b * strideB;
    C += (size_t)b * strideC;

    const int m0 = blockIdx.y * 64;
    const int n0 = blockIdx.x * 64;
    const int tx = threadIdx.x;     // 0..15
    const int ty = threadIdx.y;     // 0..15
    const int tid = ty * 16 + tx;

    __shared__ float As[16][64];
    __shared__ float Bs[16][64];

    float acc[4][4];
#pragma unroll
    for (int i = 0; i < 4; i++)
#pragma unroll
        for (int j = 0; j < 4; j++) acc[i][j] = 0.f;

    // A-load mapping: thread -> (m = tid/4, q = tid%4), loads float4 along K
    const int am = tid >> 2;
    const int aq = tid & 3;
    // B-load mapping: thread -> (kk = tid/16, n4 = (tid%16)*4)
    const int bk = tid >> 4;
    const int bn = (tid & 15) << 2;

    for (int k0 = 0; k0 < K; k0 += 16) {
        __syncthreads();
        float4 av = *(const float4*)(A + (size_t)(m0 + am) * K + k0 + aq * 4);
        As[aq * 4 + 0][am] = av.x;
        As[aq * 4 + 1][am] = av.y;
        As[aq * 4 + 2][am] = av.z;
        As[aq * 4 + 3][am] = av.w;
        *(float4*)&Bs[bk][bn] = *(const float4*)(B + (size_t)(k0 + bk) * TN + n0 + bn);
        __syncthreads();

#pragma unroll
        for (int kk = 0; kk < 16; kk++) {
            float4 a  = *(const float4*)&As[kk][ty << 2];
            float4 bb = *(const float4*)&Bs[kk][tx << 2];
            acc[0][0] += a.x * bb.x; acc[0][1] += a.x * bb.y; acc[0][2] += a.x * bb.z; acc[0][3] += a.x * bb.w;
            acc[1][0] += a.y * bb.x; acc[1][1] += a.y * bb.y; acc[1][2] += a.y * bb.z; acc[1][3] += a.y * bb.w;
            acc[2][0] += a.z * bb.x; acc[2][1] += a.z * bb.y; acc[2][2] += a.z * bb.z; acc[2][3] += a.z * bb.w;
            acc[3][0] += a.w * bb.x; acc[3][1] += a.w * bb.y; acc[3][2] += a.w * bb.z; acc[3][3] += a.w * bb.w;
        }
    }

#pragma unroll
    for (int i = 0; i < 4; i++) {
        float4 v = make_float4(acc[i][0], acc[i][1], acc[i][2], acc[i][3]);
        *(float4*)(C + (size_t)(m0 + ty * 4 + i) * TN + n0 + (tx << 2)) = v;
    }
}

// ---------------------------------------------------------------------------
// Depthwise 3x3 SAME conv + (for q/k channels) accumulate sum of squares
// block = 128 threads (one output row), grid = (H, C3, B)
// ---------------------------------------------------------------------------
__global__ __launch_bounds__(128)
void dwconv_kernel(const float* __restrict__ in, const float* __restrict__ wdw,
                   float* __restrict__ out, float* __restrict__ norm2) {
    const int y  = blockIdx.x;
    const int ch = blockIdx.y;
    const int b  = blockIdx.z;
    const int x  = threadIdx.x;

    const float* base = in + ((size_t)b * C3 + ch) * HW;

    __shared__ float rows[3][128];
    rows[0][x] = (y > 0)       ? base[(y - 1) * WW + x] : 0.f;
    rows[1][x] =                 base[y * WW + x];
    rows[2][x] = (y < HH - 1)  ? base[(y + 1) * WW + x] : 0.f;
    __syncthreads();

    float wv[9];
#pragma unroll
    for (int i = 0; i < 9; i++) wv[i] = wdw[ch * 9 + i];

    float s = 0.f;
#pragma unroll
    for (int dy = 0; dy < 3; dy++) {
#pragma unroll
        for (int dx = 0; dx < 3; dx++) {
            int xx = x + dx - 1;
            if (xx >= 0 && xx < WW) s += rows[dy][xx] * wv[dy * 3 + dx];
        }
    }
    out[((size_t)b * C3 + ch) * HW + y * WW + x] = s;

    // accumulate ||row||^2 for q (ch<192) and k (192<=ch<384) channels
    if (ch < 2 * CC) {
        float v2 = s * s;
#pragma unroll
        for (int off = 16; off > 0; off >>= 1)
            v2 += __shfl_down_sync(0xffffffffu, v2, off);
        __shared__ float wsum[4];
        if ((x & 31) == 0) wsum[x >> 5] = v2;
        __syncthreads();
        if (x == 0) {
            float t = wsum[0] + wsum[1] + wsum[2] + wsum[3];
            int idx;
            if (ch < CC) {                 // q
                idx = (b * HEADS + ch / HD) * (2 * HD) + (ch % HD);
            } else {                       // k
                int c2 = ch - CC;
                idx = (b * HEADS + c2 / HD) * (2 * HD) + HD + (c2 % HD);
            }
            atomicAdd(&norm2[idx], t);
        }
    }
}

// ---------------------------------------------------------------------------
// Gram: S[bh][i][j] += sum_p Q[i,p] * K[j,p]  (split-K over 16 chunks, atomics)
// grid = (64, 16), block = 256 (16x16, each thread 3x3 outputs)
// ---------------------------------------------------------------------------
__global__ __launch_bounds__(256)
void gram_kernel(const float* __restrict__ qkvd, float* __restrict__ S) {
    const int bh    = blockIdx.x;          // 0..63
    const int split = blockIdx.y;          // 0..15
    const int b = bh / HEADS, h = bh % HEADS;

    const float* Q  = qkvd + ((size_t)b * C3 + h * HD) * HW;
    const float* Kp = qkvd + ((size_t)b * C3 + CC + h * HD) * HW;

    __shared__ float Qs[48][33];
    __shared__ float Ks[48][33];

    const int tx = threadIdx.x & 15;       // -> 3 j's
    const int ty = threadIdx.x >> 4;       // -> 3 i's

    float acc[3][3];
#pragma unroll
    for (int i = 0; i < 3; i++)
#pragma unroll
        for (int j = 0; j < 3; j++) acc[i][j] = 0.f;

    const int p0 = split * (HW / 16);
    for (int pc = p0; pc < p0 + (HW / 16); pc += 32) {
        __syncthreads();
        for (int i = threadIdx.x; i < 48 * 32; i += 256) {
            int r = i >> 5, c = i & 31;
            Qs[r][c] = Q[(size_t)r * HW + pc + c];
            Ks[r][c] = Kp[(size_t)r * HW + pc + c];
        }
        __syncthreads();
#pragma unroll 8
        for (int kk = 0; kk < 32; kk++) {
            float a0 = Qs[ty * 3 + 0][kk];
            float a1 = Qs[ty * 3 + 1][kk];
            float a2 = Qs[ty * 3 + 2][kk];
            float b0 = Ks[tx * 3 + 0][kk];
            float b1 = Ks[tx * 3 + 1][kk];
            float b2 = Ks[tx * 3 + 2][kk];
            acc[0][0] += a0 * b0; acc[0][1] += a0 * b1; acc[0][2] += a0 * b2;
            acc[1][0] += a1 * b0; acc[1][1] += a1 * b1; acc[1][2] += a1 * b2;
            acc[2][0] += a2 * b0; acc[2][1] += a2 * b1; acc[2][2] += a2 * b2;
        }
    }

#pragma unroll
    for (int i = 0; i < 3; i++)
#pragma unroll
        for (int j = 0; j < 3; j++)
            atomicAdd(&S[((size_t)bh * HD + ty * 3 + i) * HD + tx * 3 + j], acc[i][j]);
}

// ---------------------------------------------------------------------------
// Softmax over last dim (48) with L2-norm scaling and temperature
// grid = 64 (b*h), block = 48 (one thread per row)
// ---------------------------------------------------------------------------
__global__ __launch_bounds__(48)
void softmax_kernel(float* __restrict__ S, const float* __restrict__ norm2,
                    const float* __restrict__ temperature) {
    const int bh = blockIdx.x;
    const int h  = bh % HEADS;
    const int i  = threadIdx.x;

    __shared__ float nk[48];
    const float* n2 = norm2 + bh * (2 * HD);
    nk[i] = fmaxf(sqrtf(n2[HD + i]), 1e-12f);
    __syncthreads();

    float nq = fmaxf(sqrtf(n2[i]), 1e-12f);
    float t  = temperature[h];

    float row[48];
    float mx = -1e30f;
    float* Srow = S + ((size_t)bh * HD + i) * HD;
#pragma unroll
    for (int j = 0; j < HD; j++) {
        row[j] = Srow[j] / (nq * nk[j]) * t;
        mx = fmaxf(mx, row[j]);
    }
    float sum = 0.f;
#pragma unroll
    for (int j = 0; j < HD; j++) {
        row[j] = expf(row[j] - mx);
        sum += row[j];
    }
    float inv = 1.f / sum;
#pragma unroll
    for (int j = 0; j < HD; j++) Srow[j] = row[j] * inv;
}

// ---------------------------------------------------------------------------
// M[b] = Wproj @ blockdiag(attn[b])  -> 192x192 per batch
// grid = 16, block = 256
// ---------------------------------------------------------------------------
__global__ __launch_bounds__(256)
void build_M_kernel(const float* __restrict__ Wp, const float* __restrict__ attn,
                    float* __restrict__ Mm) {
    const int b = blockIdx.x;
    for (int idx = threadIdx.x; idx < CC * CC; idx += blockDim.x) {
        int o = idx / CC, d = idx % CC;
        int h = d / HD, dl = d % HD;
        const float* wrow = Wp + o * CC + h * HD;
        const float* acol = attn + ((size_t)(b * HEADS + h) * HD) * HD + dl;
        float s = 0.f;
#pragma unroll
        for (int cl = 0; cl < HD; cl++)
            s += wrow[cl] * acol[(size_t)cl * HD];
        Mm[(size_t)b * CC * CC + idx] = s;
    }
}

// ---------------------------------------------------------------------------
// Launch
// ---------------------------------------------------------------------------
extern "C" void kernel_launch(void* const* d_in, const int* in_sizes, int n_in,
                              void* d_out, int out_size) {
    const float* x     = (const float*)d_in[0];
    const float* wqkv  = (const float*)d_in[1];
    const float* wdw   = (const float*)d_in[2];
    const float* wproj = (const float*)d_in[3];
    const float* temp  = (const float*)d_in[4];
    float* out = (float*)d_out;

    float *qkv_p, *qkvd_p, *S_p, *n2_p, *M_p;
    cudaGetSymbolAddress((void**)&qkv_p,  g_qkv);
    cudaGetSymbolAddress((void**)&qkvd_p, g_qkvd);
    cudaGetSymbolAddress((void**)&S_p,    g_S);
    cudaGetSymbolAddress((void**)&n2_p,   g_n2);
    cudaGetSymbolAddress((void**)&M_p,    g_M);

    // 0. zero accumulators
    {
        int nS = BB * HEADS * HD * HD;
        int nN = BB * HEADS * 2 * HD;
        zero_kernel<<<(nS + 255) / 256, 256>>>(S_p, nS);
        zero_kernel<<<(nN + 255) / 256, 256>>>(n2_p, nN);
    }

    // 1. qkv = Wqkv @ x   (576 x 192 x 16384 per batch)
    {
        dim3 grid(TN / 64, C3 / 64, BB);
        dim3 block(16, 16);
        gemm64<<<grid, block>>>(wqkv, x, qkv_p, C3, CC,
                                0, (size_t)CC * HW, (size_t)C3 * HW);
    }

    // 2. depthwise 3x3 + q/k norm accumulation
    {
        dim3 grid(HH, C3, BB);
        dwconv_kernel<<<grid, 128>>>(qkv_p, wdw, qkvd_p, n2_p);
    }

    // 3. Gram matrices (split-K)
    {
        dim3 grid(BB * HEADS, 16);
        gram_kernel<<<grid, 256>>>(qkvd_p, S_p);
    }

    // 4. softmax with norm scaling + temperature
    softmax_kernel<<<BB * HEADS, 48>>>(S_p, n2_p, temp);

    // 5. M = Wproj @ blockdiag(attn)
    build_M_kernel<<<BB, 256>>>(wproj, S_p, M_p);

    // 6. out = M @ v   (192 x 192 x 16384 per batch)
    {
        dim3 grid(TN / 64, CC / 64, BB);
        dim3 block(16, 16);
        gemm64<<<grid, block>>>(M_p, qkvd_p + (size_t)2 * CC * HW, out, CC, CC,
                                (size_t)CC * CC, (size_t)C3 * HW, (size_t)CC * HW);
    }
}

// round 4
// speedup vs baseline: 2.0603x; 2.0603x over previous
#include <cuda_runtime.h>
#include <cuda_bf16.h>
#include <math.h>

// Problem constants
#define BB   16
#define CC   192
#define HH   128
#define WW   128
#define HW   16384
#define C3   576
#define HEADS 4
#define HD   48
#define TN   16384

// ---------------------------------------------------------------------------
// Scratch
// ---------------------------------------------------------------------------
__device__ float g_qkv [(size_t)BB * C3 * HW];
__device__ float g_qkvd[(size_t)BB * C3 * HW];
__device__ float g_S   [BB * HEADS * HD * HD];
__device__ float g_n2  [BB * HEADS * 2 * HD];
__device__ float g_M   [BB * CC * CC];

__global__ void zero_kernel(float* a, int n) {
    int i = blockIdx.x * blockDim.x + threadIdx.x;
    if (i < n) a[i] = 0.f;
}

// ---------------------------------------------------------------------------
// tf32 tensor-core GEMM: C[M x 16384] = A[M x K] * B[K x 16384]
// 128x128 tile, BK=16, 256 threads, 8 warps as 2x4, warp tile 64x32
// mma.sync.m16n8k8.tf32, fp32 accumulate. A rows clamped / C stores predicated.
// ---------------------------------------------------------------------------
#define GBM 128
#define GBN 128
#define GBK 16
#define SPAD 8

__device__ __forceinline__ unsigned f2tf32(float x) {
    unsigned r; asm("cvt.rna.tf32.f32 %0, %1;" : "=r"(r) : "f"(x)); return r;
}

__device__ __forceinline__ void mma_tf32(float* c, const unsigned* a, const unsigned* b) {
    asm volatile(
        "mma.sync.aligned.m16n8k8.row.col.f32.tf32.tf32.f32 "
        "{%0,%1,%2,%3}, {%4,%5,%6,%7}, {%8,%9}, {%0,%1,%2,%3};"
        : "+f"(c[0]), "+f"(c[1]), "+f"(c[2]), "+f"(c[3])
        : "r"(a[0]), "r"(a[1]), "r"(a[2]), "r"(a[3]), "r"(b[0]), "r"(b[1]));
}

__global__ __launch_bounds__(256)
void gemm_tc(const float* __restrict__ A, const float* __restrict__ B,
             float* __restrict__ C, int M, int K,
             size_t sA, size_t sB, size_t sC) {
    const int bz = blockIdx.z;
    A += (size_t)bz * sA; B += (size_t)bz * sB; C += (size_t)bz * sC;
    const int m0 = blockIdx.y * GBM;
    const int n0 = blockIdx.x * GBN;
    const int tid = threadIdx.x;
    const int warp = tid >> 5, lane = tid & 31;
    const int wm = (warp >> 2) * 64;
    const int wn = (warp & 3) * 32;

    __shared__ unsigned As[GBK][GBM + SPAD];
    __shared__ unsigned Bs[GBK][GBN + SPAD];

    float acc[4][4][4];
#pragma unroll
    for (int i = 0; i < 4; i++)
#pragma unroll
        for (int j = 0; j < 4; j++)
#pragma unroll
            for (int l = 0; l < 4; l++) acc[i][j][l] = 0.f;

    const int ar = tid >> 2;             // 0..63 (A row within tile)
    const int ac = (tid & 3) << 2;       // 0,4,8,12 (A col group)
    const int brow = tid >> 5;           // 0..7 (B row)
    const int bcol = lane << 2;          // 0..124 (B col)

    float4 pa[2], pb[2];

    // prefetch k0 = 0
#pragma unroll
    for (int i = 0; i < 2; i++) {
        int r = m0 + ar + 64 * i; if (r >= M) r = M - 1;
        pa[i] = *(const float4*)(A + (size_t)r * K + ac);
        pb[i] = *(const float4*)(B + (size_t)(brow + 8 * i) * TN + n0 + bcol);
    }

    for (int k0 = 0; k0 < K; k0 += GBK) {
        // store prefetched tile into smem (converted to tf32)
#pragma unroll
        for (int i = 0; i < 2; i++) {
            As[ac + 0][ar + 64 * i] = f2tf32(pa[i].x);
            As[ac + 1][ar + 64 * i] = f2tf32(pa[i].y);
            As[ac + 2][ar + 64 * i] = f2tf32(pa[i].z);
            As[ac + 3][ar + 64 * i] = f2tf32(pa[i].w);
            uint4 t = make_uint4(f2tf32(pb[i].x), f2tf32(pb[i].y),
                                 f2tf32(pb[i].z), f2tf32(pb[i].w));
            *(uint4*)&Bs[brow + 8 * i][bcol] = t;
        }
        __syncthreads();

        if (k0 + GBK < K) {
#pragma unroll
            for (int i = 0; i < 2; i++) {
                int r = m0 + ar + 64 * i; if (r >= M) r = M - 1;
                pa[i] = *(const float4*)(A + (size_t)r * K + k0 + GBK + ac);
                pb[i] = *(const float4*)(B + (size_t)(k0 + GBK + brow + 8 * i) * TN + n0 + bcol);
            }
        }

        const int frow = lane >> 2;      // 0..7
        const int fcol = lane & 3;       // 0..3
#pragma unroll
        for (int ks = 0; ks < GBK; ks += 8) {
            unsigned af[4][4];
#pragma unroll
            for (int mt = 0; mt < 4; mt++) {
                int mb = wm + mt * 16 + frow;
                af[mt][0] = As[ks + fcol][mb];
                af[mt][1] = As[ks + fcol][mb + 8];
                af[mt][2] = As[ks + 4 + fcol][mb];
                af[mt][3] = As[ks + 4 + fcol][mb + 8];
            }
            unsigned bf[4][2];
#pragma unroll
            for (int nt = 0; nt < 4; nt++) {
                int nb = wn + nt * 8 + frow;
                bf[nt][0] = Bs[ks + fcol][nb];
                bf[nt][1] = Bs[ks + 4 + fcol][nb];
            }
#pragma unroll
            for (int mt = 0; mt < 4; mt++)
#pragma unroll
                for (int nt = 0; nt < 4; nt++)
                    mma_tf32(acc[mt][nt], af[mt], bf[nt]);
        }
        __syncthreads();
    }

    // epilogue
    const int frow = lane >> 2;
    const int qc = (lane & 3) * 2;
#pragma unroll
    for (int mt = 0; mt < 4; mt++) {
        int gr = m0 + wm + mt * 16 + frow;
#pragma unroll
        for (int nt = 0; nt < 4; nt++) {
            int gc = n0 + wn + nt * 8 + qc;
            if (gr < M)
                *(float2*)(C + (size_t)gr * TN + gc) = make_float2(acc[mt][nt][0], acc[mt][nt][1]);
            if (gr + 8 < M)
                *(float2*)(C + (size_t)(gr + 8) * TN + gc) = make_float2(acc[mt][nt][2], acc[mt][nt][3]);
        }
    }
}

// ---------------------------------------------------------------------------
// Tiled depthwise 3x3 + q/k norm accumulation
// block = 256, tile = 32 rows x 128 cols, grid = (4, C3, B)
// ---------------------------------------------------------------------------
__global__ __launch_bounds__(256)
void dwconv2(const float* __restrict__ in, const float* __restrict__ wdw,
             float* __restrict__ out, float* __restrict__ norm2) {
    const int y0 = blockIdx.x * 32;
    const int ch = blockIdx.y;
    const int b  = blockIdx.z;
    const float* base = in + ((size_t)b * C3 + ch) * HW;
    float* obase = out + ((size_t)b * C3 + ch) * HW;

    __shared__ float t[34][128];
    for (int i = threadIdx.x; i < 34 * 128; i += 256) {
        int r = i >> 7, c = i & 127;
        int gy = y0 - 1 + r;
        t[r][c] = (gy >= 0 && gy < HH) ? base[gy * WW + c] : 0.f;
    }
    __syncthreads();

    float w[9];
#pragma unroll
    for (int i = 0; i < 9; i++) w[i] = wdw[ch * 9 + i];

    const int x  = threadIdx.x & 127;
    const int ry = threadIdx.x >> 7;   // 0..1

    float ss = 0.f;
#pragma unroll
    for (int j = 0; j < 16; j++) {
        int y = ry * 16 + j;           // local out row (smem center = y+1)
        float s = 0.f;
#pragma unroll
        for (int dy = 0; dy < 3; dy++) {
            const float* rr = t[y + dy];
            if (x > 0)   s += rr[x - 1] * w[dy * 3 + 0];
            s += rr[x] * w[dy * 3 + 1];
            if (x < 127) s += rr[x + 1] * w[dy * 3 + 2];
        }
        obase[(y0 + y) * WW + x] = s;
        ss += s * s;
    }

    if (ch < 2 * CC) {
#pragma unroll
        for (int off = 16; off > 0; off >>= 1)
            ss += __shfl_down_sync(0xffffffffu, ss, off);
        __shared__ float wsum[8];
        if ((threadIdx.x & 31) == 0) wsum[threadIdx.x >> 5] = ss;
        __syncthreads();
        if (threadIdx.x == 0) {
            float tsum = 0.f;
#pragma unroll
            for (int i = 0; i < 8; i++) tsum += wsum[i];
            int idx;
            if (ch < CC) idx = (b * HEADS + ch / HD) * (2 * HD) + (ch % HD);
            else { int c2 = ch - CC; idx = (b * HEADS + c2 / HD) * (2 * HD) + HD + (c2 % HD); }
            atomicAdd(&norm2[idx], tsum);
        }
    }
}

// ---------------------------------------------------------------------------
// Gram: S[bh][i][j] += sum_p Q[i,p]*K[j,p]   (split-K, atomics)
// ---------------------------------------------------------------------------
__global__ __launch_bounds__(256)
void gram_kernel(const float* __restrict__ qkvd, float* __restrict__ S) {
    const int bh    = blockIdx.x;
    const int split = blockIdx.y;
    const int b = bh / HEADS, h = bh % HEADS;

    const float* Q  = qkvd + ((size_t)b * C3 + h * HD) * HW;
    const float* Kp = qkvd + ((size_t)b * C3 + CC + h * HD) * HW;

    __shared__ float Qs[48][33];
    __shared__ float Ks[48][33];

    const int tx = threadIdx.x & 15;
    const int ty = threadIdx.x >> 4;

    float acc[3][3];
#pragma unroll
    for (int i = 0; i < 3; i++)
#pragma unroll
        for (int j = 0; j < 3; j++) acc[i][j] = 0.f;

    const int p0 = split * (HW / 16);
    for (int pc = p0; pc < p0 + (HW / 16); pc += 32) {
        __syncthreads();
        for (int i = threadIdx.x; i < 48 * 32; i += 256) {
            int r = i >> 5, c = i & 31;
            Qs[r][c] = Q[(size_t)r * HW + pc + c];
            Ks[r][c] = Kp[(size_t)r * HW + pc + c];
        }
        __syncthreads();
#pragma unroll 8
        for (int kk = 0; kk < 32; kk++) {
            float a0 = Qs[ty * 3 + 0][kk];
            float a1 = Qs[ty * 3 + 1][kk];
            float a2 = Qs[ty * 3 + 2][kk];
            float b0 = Ks[tx * 3 + 0][kk];
            float b1 = Ks[tx * 3 + 1][kk];
            float b2 = Ks[tx * 3 + 2][kk];
            acc[0][0] += a0 * b0; acc[0][1] += a0 * b1; acc[0][2] += a0 * b2;
            acc[1][0] += a1 * b0; acc[1][1] += a1 * b1; acc[1][2] += a1 * b2;
            acc[2][0] += a2 * b0; acc[2][1] += a2 * b1; acc[2][2] += a2 * b2;
        }
    }

#pragma unroll
    for (int i = 0; i < 3; i++)
#pragma unroll
        for (int j = 0; j < 3; j++)
            atomicAdd(&S[((size_t)bh * HD + ty * 3 + i) * HD + tx * 3 + j], acc[i][j]);
}

// ---------------------------------------------------------------------------
// Softmax (48 wide) with L2-norm scaling + temperature
// ---------------------------------------------------------------------------
__global__ __launch_bounds__(48)
void softmax_kernel(float* __restrict__ S, const float* __restrict__ norm2,
                    const float* __restrict__ temperature) {
    const int bh = blockIdx.x;
    const int h  = bh % HEADS;
    const int i  = threadIdx.x;

    __shared__ float nk[48];
    const float* n2 = norm2 + bh * (2 * HD);
    nk[i] = fmaxf(sqrtf(n2[HD + i]), 1e-12f);
    __syncthreads();

    float nq = fmaxf(sqrtf(n2[i]), 1e-12f);
    float t  = temperature[h];

    float row[48];
    float mx = -1e30f;
    float* Srow = S + ((size_t)bh * HD + i) * HD;
#pragma unroll
    for (int j = 0; j < HD; j++) {
        row[j] = Srow[j] / (nq * nk[j]) * t;
        mx = fmaxf(mx, row[j]);
    }
    float sum = 0.f;
#pragma unroll
    for (int j = 0; j < HD; j++) {
        row[j] = expf(row[j] - mx);
        sum += row[j];
    }
    float inv = 1.f / sum;
#pragma unroll
    for (int j = 0; j < HD; j++) Srow[j] = row[j] * inv;
}

// ---------------------------------------------------------------------------
// M[b] = Wproj @ blockdiag(attn[b])
// ---------------------------------------------------------------------------
__global__ __launch_bounds__(256)
void build_M_kernel(const float* __restrict__ Wp, const float* __restrict__ attn,
                    float* __restrict__ Mm) {
    const int b = blockIdx.x;
    for (int idx = threadIdx.x; idx < CC * CC; idx += blockDim.x) {
        int o = idx / CC, d = idx % CC;
        int h = d / HD, dl = d % HD;
        const float* wrow = Wp + o * CC + h * HD;
        const float* acol = attn + ((size_t)(b * HEADS + h) * HD) * HD + dl;
        float s = 0.f;
#pragma unroll
        for (int cl = 0; cl < HD; cl++)
            s += wrow[cl] * acol[(size_t)cl * HD];
        Mm[(size_t)b * CC * CC + idx] = s;
    }
}

// ---------------------------------------------------------------------------
// Launch
// ---------------------------------------------------------------------------
extern "C" void kernel_launch(void* const* d_in, const int* in_sizes, int n_in,
                              void* d_out, int out_size) {
    const float* x     = (const float*)d_in[0];
    const float* wqkv  = (const float*)d_in[1];
    const float* wdw   = (const float*)d_in[2];
    const float* wproj = (const float*)d_in[3];
    const float* temp  = (const float*)d_in[4];
    float* out = (float*)d_out;

    float *qkv_p, *qkvd_p, *S_p, *n2_p, *M_p;
    cudaGetSymbolAddress((void**)&qkv_p,  g_qkv);
    cudaGetSymbolAddress((void**)&qkvd_p, g_qkvd);
    cudaGetSymbolAddress((void**)&S_p,    g_S);
    cudaGetSymbolAddress((void**)&n2_p,   g_n2);
    cudaGetSymbolAddress((void**)&M_p,    g_M);

    // 0. zero accumulators
    {
        int nS = BB * HEADS * HD * HD;
        int nN = BB * HEADS * 2 * HD;
        zero_kernel<<<(nS + 255) / 256, 256>>>(S_p, nS);
        zero_kernel<<<(nN + 255) / 256, 256>>>(n2_p, nN);
    }

    // 1. qkv = Wqkv @ x   (576 x 192 x 16384, tf32 tensor cores)
    {
        dim3 grid(TN / GBN, (C3 + GBM - 1) / GBM, BB);
        gemm_tc<<<grid, 256>>>(wqkv, x, qkv_p, C3, CC,
                               0, (size_t)CC * HW, (size_t)C3 * HW);
    }

    // 2. depthwise 3x3 + q/k norm accumulation (tiled)
    {
        dim3 grid(HH / 32, C3, BB);
        dwconv2<<<grid, 256>>>(qkv_p, wdw, qkvd_p, n2_p);
    }

    // 3. Gram matrices
    {
        dim3 grid(BB * HEADS, 16);
        gram_kernel<<<grid, 256>>>(qkvd_p, S_p);
    }

    // 4. softmax
    softmax_kernel<<<BB * HEADS, 48>>>(S_p, n2_p, temp);

    // 5. M = Wproj @ blockdiag(attn)
    build_M_kernel<<<BB, 256>>>(wproj, S_p, M_p);

    // 6. out = M @ v   (192 x 192 x 16384, tf32 tensor cores)
    {
        dim3 grid(TN / GBN, (CC + GBM - 1) / GBM, BB);
        gemm_tc<<<grid, 256>>>(M_p, qkvd_p + (size_t)2 * CC * HW, out, CC, CC,
                               (size_t)CC * CC, (size_t)C3 * HW, (size_t)CC * HW);
    }
}

// round 5
// speedup vs baseline: 2.1518x; 1.0444x over previous
#include <cuda_runtime.h>
#include <cuda_bf16.h>
#include <math.h>

// Problem constants
#define BB   16
#define CC   192
#define HH   128
#define WW   128
#define HW   16384
#define C3   576
#define HEADS 4
#define HD   48
#define TN   16384

// ---------------------------------------------------------------------------
// Scratch
// ---------------------------------------------------------------------------
__device__ float g_qkv [(size_t)BB * C3 * HW];
__device__ float g_qkvd[(size_t)BB * C3 * HW];
__device__ float g_S   [BB * HEADS * HD * HD];
__device__ float g_n2  [BB * HEADS * 2 * HD];
__device__ float g_M   [BB * CC * CC];

__global__ void zero_kernel(float* a, int n) {
    int i = blockIdx.x * blockDim.x + threadIdx.x;
    if (i < n) a[i] = 0.f;
}

// ---------------------------------------------------------------------------
// tf32 tensor-core GEMM v2: C[M x 16384] = A[M x K] * B[K x 16384]
// 128x128 tile, BK=16, 256 threads, 8 warps (2x4), warp tile 64x32.
// 2-stage cp.async pipeline; fp32 in smem; cvt->tf32 at fragment load.
// ---------------------------------------------------------------------------
#define GBM 128
#define GBN 128
#define GBK 16

__device__ __forceinline__ unsigned f2tf32(float x) {
    unsigned r; asm("cvt.rna.tf32.f32 %0, %1;" : "=r"(r) : "f"(x)); return r;
}

__device__ __forceinline__ void mma_tf32(float* c, const unsigned* a, const unsigned* b) {
    asm volatile(
        "mma.sync.aligned.m16n8k8.row.col.f32.tf32.tf32.f32 "
        "{%0,%1,%2,%3}, {%4,%5,%6,%7}, {%8,%9}, {%0,%1,%2,%3};"
        : "+f"(c[0]), "+f"(c[1]), "+f"(c[2]), "+f"(c[3])
        : "r"(a[0]), "r"(a[1]), "r"(a[2]), "r"(a[3]), "r"(b[0]), "r"(b[1]));
}

__device__ __forceinline__ void cpasync16(void* smem, const void* g) {
    unsigned s = (unsigned)__cvta_generic_to_shared(smem);
    asm volatile("cp.async.ca.shared.global [%0], [%1], 16;" :: "r"(s), "l"(g));
}
__device__ __forceinline__ void cp_commit() {
    asm volatile("cp.async.commit_group;");
}
template <int N>
__device__ __forceinline__ void cp_wait() {
    asm volatile("cp.async.wait_group %0;" :: "n"(N));
}

__global__ __launch_bounds__(256)
void gemm_tc(const float* __restrict__ A, const float* __restrict__ B,
             float* __restrict__ C, int M, int K,
             size_t sA, size_t sB, size_t sC) {
    const int bz = blockIdx.z;
    A += (size_t)bz * sA; B += (size_t)bz * sB; C += (size_t)bz * sC;
    const int m0 = blockIdx.y * GBM;
    const int n0 = blockIdx.x * GBN;
    const int tid = threadIdx.x;
    const int warp = tid >> 5, lane = tid & 31;
    const int wm = (warp >> 2) * 64;
    const int wn = (warp & 3) * 32;

    __shared__ float As[2][GBM][GBK + 4];   // [stage][m][k]
    __shared__ float Bs[2][GBK][GBN + 4];   // [stage][k][n]

    float acc[4][4][4];
#pragma unroll
    for (int i = 0; i < 4; i++)
#pragma unroll
        for (int j = 0; j < 4; j++)
#pragma unroll
            for (int l = 0; l < 4; l++) acc[i][j][l] = 0.f;

    // async copy of one stage: A tile 128x16 (512 f4), B tile 16x128 (512 f4)
    auto issue = [&](int k0, int st) {
#pragma unroll
        for (int i = 0; i < 2; i++) {
            int idx = tid * 2 + i;
            int row = idx >> 2, cq = (idx & 3) << 2;
            int r = m0 + row; if (r >= M) r = M - 1;
            cpasync16(&As[st][row][cq], A + (size_t)r * K + k0 + cq);
        }
#pragma unroll
        for (int i = 0; i < 2; i++) {
            int idx = tid * 2 + i;
            int r = idx >> 5, cq = (idx & 31) << 2;
            cpasync16(&Bs[st][r][cq], B + (size_t)(k0 + r) * TN + n0 + cq);
        }
        cp_commit();
    };

    issue(0, 0);
    issue(GBK, 1);

    const int frow = lane >> 2;          // 0..7
    const int fcol = lane & 3;           // 0..3

    int st = 0;
    for (int k0 = 0; k0 < K; k0 += GBK) {
        cp_wait<1>();
        __syncthreads();

#pragma unroll
        for (int ks = 0; ks < GBK; ks += 8) {
            unsigned af[4][4];
#pragma unroll
            for (int mt = 0; mt < 4; mt++) {
                int mb = wm + mt * 16 + frow;
                af[mt][0] = f2tf32(As[st][mb][ks + fcol]);
                af[mt][1] = f2tf32(As[st][mb + 8][ks + fcol]);
                af[mt][2] = f2tf32(As[st][mb][ks + 4 + fcol]);
                af[mt][3] = f2tf32(As[st][mb + 8][ks + 4 + fcol]);
            }
            unsigned bf[4][2];
#pragma unroll
            for (int nt = 0; nt < 4; nt++) {
                int nb = wn + nt * 8 + frow;
                bf[nt][0] = f2tf32(Bs[st][ks + fcol][nb]);
                bf[nt][1] = f2tf32(Bs[st][ks + 4 + fcol][nb]);
            }
#pragma unroll
            for (int mt = 0; mt < 4; mt++)
#pragma unroll
                for (int nt = 0; nt < 4; nt++)
                    mma_tf32(acc[mt][nt], af[mt], bf[nt]);
        }
        __syncthreads();

        if (k0 + 2 * GBK < K) issue(k0 + 2 * GBK, st);
        else cp_commit();                 // keep one group per iteration
        st ^= 1;
    }

    // epilogue
    const int qc = (lane & 3) * 2;
#pragma unroll
    for (int mt = 0; mt < 4; mt++) {
        int gr = m0 + wm + mt * 16 + frow;
#pragma unroll
        for (int nt = 0; nt < 4; nt++) {
            int gc = n0 + wn + nt * 8 + qc;
            if (gr < M)
                *(float2*)(C + (size_t)gr * TN + gc) = make_float2(acc[mt][nt][0], acc[mt][nt][1]);
            if (gr + 8 < M)
                *(float2*)(C + (size_t)(gr + 8) * TN + gc) = make_float2(acc[mt][nt][2], acc[mt][nt][3]);
        }
    }
}

// ---------------------------------------------------------------------------
// Depthwise 3x3 v3: zero-padded smem tile, 4 pixels/thread, float4 I/O
// block = 256, tile = 32 rows x 128 cols, grid = (4, C3, B)
// ---------------------------------------------------------------------------
__global__ __launch_bounds__(256)
void dwconv3(const float* __restrict__ in, const float* __restrict__ wdw,
             float* __restrict__ out, float* __restrict__ norm2) {
    const int y0 = blockIdx.x * 32;
    const int ch = blockIdx.y;
    const int b  = blockIdx.z;
    const float* base = in + ((size_t)b * C3 + ch) * HW;
    float* obase = out + ((size_t)b * C3 + ch) * HW;

    __shared__ float t[34][136];   // data cols [4..131]; col 3 / col 132 = zero pads

    // zero pads
    if (threadIdx.x < 34) {
        t[threadIdx.x][3]   = 0.f;
        t[threadIdx.x][132] = 0.f;
    }
    // load 34 rows x 32 float4
    for (int i = threadIdx.x; i < 34 * 32; i += 256) {
        int r = i >> 5, j = i & 31;
        int gy = y0 - 1 + r;
        float4 v = make_float4(0.f, 0.f, 0.f, 0.f);
        if (gy >= 0 && gy < HH) v = *(const float4*)(base + gy * WW + 4 * j);
        *(float4*)&t[r][4 + 4 * j] = v;
    }
    __syncthreads();

    float w[9];
#pragma unroll
    for (int i = 0; i < 9; i++) w[i] = wdw[ch * 9 + i];

    const int ry = threadIdx.x >> 5;   // 0..7 (4 rows each)
    const int x0 = (threadIdx.x & 31) << 2;
    const int c  = 4 + x0;

    float ss = 0.f;
#pragma unroll
    for (int jj = 0; jj < 4; jj++) {
        int y = ry * 4 + jj;
        float4 o = make_float4(0.f, 0.f, 0.f, 0.f);
#pragma unroll
        for (int dy = 0; dy < 3; dy++) {
            const float* rr = t[y + dy];
            float4 v = *(const float4*)&rr[c];
            float  l = rr[c - 1];
            float  rg = rr[c + 4];
            float w0 = w[dy * 3 + 0], w1 = w[dy * 3 + 1], w2 = w[dy * 3 + 2];
            o.x += l   * w0 + v.x * w1 + v.y * w2;
            o.y += v.x * w0 + v.y * w1 + v.z * w2;
            o.z += v.y * w0 + v.z * w1 + v.w * w2;
            o.w += v.z * w0 + v.w * w1 + rg  * w2;
        }
        *(float4*)(obase + (y0 + y) * WW + x0) = o;
        ss += o.x * o.x + o.y * o.y + o.z * o.z + o.w * o.w;
    }

    if (ch < 2 * CC) {
#pragma unroll
        for (int off = 16; off > 0; off >>= 1)
            ss += __shfl_down_sync(0xffffffffu, ss, off);
        __shared__ float wsum[8];
        if ((threadIdx.x & 31) == 0) wsum[threadIdx.x >> 5] = ss;
        __syncthreads();
        if (threadIdx.x == 0) {
            float tsum = 0.f;
#pragma unroll
            for (int i = 0; i < 8; i++) tsum += wsum[i];
            int idx;
            if (ch < CC) idx = (b * HEADS + ch / HD) * (2 * HD) + (ch % HD);
            else { int c2 = ch - CC; idx = (b * HEADS + c2 / HD) * (2 * HD) + HD + (c2 % HD); }
            atomicAdd(&norm2[idx], tsum);
        }
    }
}

// ---------------------------------------------------------------------------
// Gram: S[bh][i][j] += sum_p Q[i,p]*K[j,p]   (split-K, atomics)
// ---------------------------------------------------------------------------
__global__ __launch_bounds__(256)
void gram_kernel(const float* __restrict__ qkvd, float* __restrict__ S) {
    const int bh    = blockIdx.x;
    const int split = blockIdx.y;
    const int b = bh / HEADS, h = bh % HEADS;

    const float* Q  = qkvd + ((size_t)b * C3 + h * HD) * HW;
    const float* Kp = qkvd + ((size_t)b * C3 + CC + h * HD) * HW;

    __shared__ float Qs[48][33];
    __shared__ float Ks[48][33];

    const int tx = threadIdx.x & 15;
    const int ty = threadIdx.x >> 4;

    float acc[3][3];
#pragma unroll
    for (int i = 0; i < 3; i++)
#pragma unroll
        for (int j = 0; j < 3; j++) acc[i][j] = 0.f;

    const int p0 = split * (HW / 16);
    for (int pc = p0; pc < p0 + (HW / 16); pc += 32) {
        __syncthreads();
        for (int i = threadIdx.x; i < 48 * 32; i += 256) {
            int r = i >> 5, c = i & 31;
            Qs[r][c] = Q[(size_t)r * HW + pc + c];
            Ks[r][c] = Kp[(size_t)r * HW + pc + c];
        }
        __syncthreads();
#pragma unroll 8
        for (int kk = 0; kk < 32; kk++) {
            float a0 = Qs[ty * 3 + 0][kk];
            float a1 = Qs[ty * 3 + 1][kk];
            float a2 = Qs[ty * 3 + 2][kk];
            float b0 = Ks[tx * 3 + 0][kk];
            float b1 = Ks[tx * 3 + 1][kk];
            float b2 = Ks[tx * 3 + 2][kk];
            acc[0][0] += a0 * b0; acc[0][1] += a0 * b1; acc[0][2] += a0 * b2;
            acc[1][0] += a1 * b0; acc[1][1] += a1 * b1; acc[1][2] += a1 * b2;
            acc[2][0] += a2 * b0; acc[2][1] += a2 * b1; acc[2][2] += a2 * b2;
        }
    }

#pragma unroll
    for (int i = 0; i < 3; i++)
#pragma unroll
        for (int j = 0; j < 3; j++)
            atomicAdd(&S[((size_t)bh * HD + ty * 3 + i) * HD + tx * 3 + j], acc[i][j]);
}

// ---------------------------------------------------------------------------
// Softmax (48 wide) with L2-norm scaling + temperature
// ---------------------------------------------------------------------------
__global__ __launch_bounds__(48)
void softmax_kernel(float* __restrict__ S, const float* __restrict__ norm2,
                    const float* __restrict__ temperature) {
    const int bh = blockIdx.x;
    const int h  = bh % HEADS;
    const int i  = threadIdx.x;

    __shared__ float nk[48];
    const float* n2 = norm2 + bh * (2 * HD);
    nk[i] = fmaxf(sqrtf(n2[HD + i]), 1e-12f);
    __syncthreads();

    float nq = fmaxf(sqrtf(n2[i]), 1e-12f);
    float t  = temperature[h];

    float row[48];
    float mx = -1e30f;
    float* Srow = S + ((size_t)bh * HD + i) * HD;
#pragma unroll
    for (int j = 0; j < HD; j++) {
        row[j] = Srow[j] / (nq * nk[j]) * t;
        mx = fmaxf(mx, row[j]);
    }
    float sum = 0.f;
#pragma unroll
    for (int j = 0; j < HD; j++) {
        row[j] = expf(row[j] - mx);
        sum += row[j];
    }
    float inv = 1.f / sum;
#pragma unroll
    for (int j = 0; j < HD; j++) Srow[j] = row[j] * inv;
}

// ---------------------------------------------------------------------------
// M[b] = Wproj @ blockdiag(attn[b])
// ---------------------------------------------------------------------------
__global__ __launch_bounds__(256)
void build_M_kernel(const float* __restrict__ Wp, const float* __restrict__ attn,
                    float* __restrict__ Mm) {
    const int b = blockIdx.x;
    for (int idx = threadIdx.x; idx < CC * CC; idx += blockDim.x) {
        int o = idx / CC, d = idx % CC;
        int h = d / HD, dl = d % HD;
        const float* wrow = Wp + o * CC + h * HD;
        const float* acol = attn + ((size_t)(b * HEADS + h) * HD) * HD + dl;
        float s = 0.f;
#pragma unroll
        for (int cl = 0; cl < HD; cl++)
            s += wrow[cl] * acol[(size_t)cl * HD];
        Mm[(size_t)b * CC * CC + idx] = s;
    }
}

// ---------------------------------------------------------------------------
// Launch
// ---------------------------------------------------------------------------
extern "C" void kernel_launch(void* const* d_in, const int* in_sizes, int n_in,
                              void* d_out, int out_size) {
    const float* x     = (const float*)d_in[0];
    const float* wqkv  = (const float*)d_in[1];
    const float* wdw   = (const float*)d_in[2];
    const float* wproj = (const float*)d_in[3];
    const float* temp  = (const float*)d_in[4];
    float* out = (float*)d_out;

    float *qkv_p, *qkvd_p, *S_p, *n2_p, *M_p;
    cudaGetSymbolAddress((void**)&qkv_p,  g_qkv);
    cudaGetSymbolAddress((void**)&qkvd_p, g_qkvd);
    cudaGetSymbolAddress((void**)&S_p,    g_S);
    cudaGetSymbolAddress((void**)&n2_p,   g_n2);
    cudaGetSymbolAddress((void**)&M_p,    g_M);

    // 0. zero accumulators
    {
        int nS = BB * HEADS * HD * HD;
        int nN = BB * HEADS * 2 * HD;
        zero_kernel<<<(nS + 255) / 256, 256>>>(S_p, nS);
        zero_kernel<<<(nN + 255) / 256, 256>>>(n2_p, nN);
    }

    // 1. qkv = Wqkv @ x   (576 x 192 x 16384, tf32 tensor cores)
    {
        dim3 grid(TN / GBN, (C3 + GBM - 1) / GBM, BB);
        gemm_tc<<<grid, 256>>>(wqkv, x, qkv_p, C3, CC,
                               0, (size_t)CC * HW, (size_t)C3 * HW);
    }

    // 2. depthwise 3x3 + q/k norm accumulation (tiled, vectorized)
    {
        dim3 grid(HH / 32, C3, BB);
        dwconv3<<<grid, 256>>>(qkv_p, wdw, qkvd_p, n2_p);
    }

    // 3. Gram matrices
    {
        dim3 grid(BB * HEADS, 16);
        gram_kernel<<<grid, 256>>>(qkvd_p, S_p);
    }

    // 4. softmax
    softmax_kernel<<<BB * HEADS, 48>>>(S_p, n2_p, temp);

    // 5. M = Wproj @ blockdiag(attn)
    build_M_kernel<<<BB, 256>>>(wproj, S_p, M_p);

    // 6. out = M @ v   (192 x 192 x 16384, tf32 tensor cores)
    {
        dim3 grid(TN / GBN, (CC + GBM - 1) / GBM, BB);
        gemm_tc<<<grid, 256>>>(M_p, qkvd_p + (size_t)2 * CC * HW, out, CC, CC,
                               (size_t)CC * CC, (size_t)C3 * HW, (size_t)CC * HW);
    }
}

// round 6
// speedup vs baseline: 2.1600x; 1.0038x over previous
#include <cuda_runtime.h>
#include <cuda_bf16.h>
#include <math.h>

// Problem constants
#define BB   16
#define CC   192
#define HH   128
#define WW   128
#define HW   16384
#define C3   576
#define HEADS 4
#define HD   48
#define TN   16384

// ---------------------------------------------------------------------------
// Scratch
// ---------------------------------------------------------------------------
__device__ float g_qkv [(size_t)BB * C3 * HW];
__device__ float g_qkvd[(size_t)BB * C3 * HW];
__device__ float g_S   [BB * HEADS * HD * HD];
__device__ float g_n2  [BB * HEADS * 2 * HD];
__device__ float g_M   [BB * CC * CC];

__global__ void zero_kernel(float* a, int n) {
    int i = blockIdx.x * blockDim.x + threadIdx.x;
    if (i < n) a[i] = 0.f;
}

// ---------------------------------------------------------------------------
// tf32 tensor-core GEMM v3: C[M x 16384] = A[M x K] * B[K x 16384]
// 128x128 tile, BK=16, 256 threads, 8 warps (2x4), warp tile 64x32.
// 4-stage cp.async pipeline (dynamic smem); grid.x = M-tile so a wave
// co-schedules all M-tiles of the same B columns -> B served from L2.
// ---------------------------------------------------------------------------
#define GBM 128
#define GBN 128
#define GBK 16
#define STAGES 4
#define APITCH 20          // 128 rows x 20 floats (80B stride, 16B aligned)
#define BPITCH 132         // 16 rows x 132 floats (528B stride, 16B aligned)
#define SMEM_GEMM ((STAGES * GBM * APITCH + STAGES * GBK * BPITCH) * 4)

#define AS(st, m, k) As[(st) * GBM * APITCH + (m) * APITCH + (k)]
#define BS(st, k, n) Bs[(st) * GBK * BPITCH + (k) * BPITCH + (n)]

__device__ __forceinline__ unsigned f2tf32(float x) {
    unsigned r; asm("cvt.rna.tf32.f32 %0, %1;" : "=r"(r) : "f"(x)); return r;
}

__device__ __forceinline__ void mma_tf32(float* c, const unsigned* a, const unsigned* b) {
    asm volatile(
        "mma.sync.aligned.m16n8k8.row.col.f32.tf32.tf32.f32 "
        "{%0,%1,%2,%3}, {%4,%5,%6,%7}, {%8,%9}, {%0,%1,%2,%3};"
        : "+f"(c[0]), "+f"(c[1]), "+f"(c[2]), "+f"(c[3])
        : "r"(a[0]), "r"(a[1]), "r"(a[2]), "r"(a[3]), "r"(b[0]), "r"(b[1]));
}

__device__ __forceinline__ void cpasync16(void* smem, const void* g) {
    unsigned s = (unsigned)__cvta_generic_to_shared(smem);
    asm volatile("cp.async.ca.shared.global [%0], [%1], 16;" :: "r"(s), "l"(g));
}
__device__ __forceinline__ void cp_commit() {
    asm volatile("cp.async.commit_group;");
}
template <int N>
__device__ __forceinline__ void cp_wait() {
    asm volatile("cp.async.wait_group %0;" :: "n"(N));
}

__global__ __launch_bounds__(256)
void gemm_tc(const float* __restrict__ A, const float* __restrict__ B,
             float* __restrict__ C, int M, int K,
             size_t sA, size_t sB, size_t sC) {
    extern __shared__ float smem[];
    float* As = smem;
    float* Bs = smem + STAGES * GBM * APITCH;

    const int bz = blockIdx.z;
    A += (size_t)bz * sA; B += (size_t)bz * sB; C += (size_t)bz * sC;
    const int m0 = blockIdx.x * GBM;       // M fastest for L2 reuse of B
    const int n0 = blockIdx.y * GBN;
    const int tid = threadIdx.x;
    const int warp = tid >> 5, lane = tid & 31;
    const int wm = (warp >> 2) * 64;
    const int wn = (warp & 3) * 32;

    float acc[4][4][4];
#pragma unroll
    for (int i = 0; i < 4; i++)
#pragma unroll
        for (int j = 0; j < 4; j++)
#pragma unroll
            for (int l = 0; l < 4; l++) acc[i][j][l] = 0.f;

    const int NK = K / GBK;

    auto issue = [&](int ki) {
        int st = ki & (STAGES - 1);
        int k0 = ki * GBK;
#pragma unroll
        for (int i = 0; i < 2; i++) {
            int idx = tid * 2 + i;            // 0..511: A tile 128x16 = 512 f4
            int row = idx >> 2, cq = (idx & 3) << 2;
            int r = m0 + row; if (r >= M) r = M - 1;
            cpasync16(&AS(st, row, cq), A + (size_t)r * K + k0 + cq);
        }
#pragma unroll
        for (int i = 0; i < 2; i++) {
            int idx = tid * 2 + i;            // B tile 16x128 = 512 f4
            int r = idx >> 5, cq = (idx & 31) << 2;
            cpasync16(&BS(st, r, cq), B + (size_t)(k0 + r) * TN + n0 + cq);
        }
        cp_commit();
    };

    issue(0); issue(1); issue(2);

    const int frow = lane >> 2;          // 0..7
    const int fcol = lane & 3;           // 0..3

    for (int ki = 0; ki < NK; ki++) {
        cp_wait<2>();
        __syncthreads();
        const int st = ki & (STAGES - 1);

#pragma unroll
        for (int ks = 0; ks < GBK; ks += 8) {
            unsigned af[4][4];
#pragma unroll
            for (int mt = 0; mt < 4; mt++) {
                int mb = wm + mt * 16 + frow;
                af[mt][0] = f2tf32(AS(st, mb,     ks + fcol));
                af[mt][1] = f2tf32(AS(st, mb + 8, ks + fcol));
                af[mt][2] = f2tf32(AS(st, mb,     ks + 4 + fcol));
                af[mt][3] = f2tf32(AS(st, mb + 8, ks + 4 + fcol));
            }
            unsigned bf[4][2];
#pragma unroll
            for (int nt = 0; nt < 4; nt++) {
                int nb = wn + nt * 8 + frow;
                bf[nt][0] = f2tf32(BS(st, ks + fcol,     nb));
                bf[nt][1] = f2tf32(BS(st, ks + 4 + fcol, nb));
            }
#pragma unroll
            for (int mt = 0; mt < 4; mt++)
#pragma unroll
                for (int nt = 0; nt < 4; nt++)
                    mma_tf32(acc[mt][nt], af[mt], bf[nt]);
        }
        __syncthreads();

        if (ki + 3 < NK) issue(ki + 3);
        else cp_commit();                 // keep one group per iteration
    }

    // epilogue
    const int qc = (lane & 3) * 2;
#pragma unroll
    for (int mt = 0; mt < 4; mt++) {
        int gr = m0 + wm + mt * 16 + frow;
#pragma unroll
        for (int nt = 0; nt < 4; nt++) {
            int gc = n0 + wn + nt * 8 + qc;
            if (gr < M)
                *(float2*)(C + (size_t)gr * TN + gc) = make_float2(acc[mt][nt][0], acc[mt][nt][1]);
            if (gr + 8 < M)
                *(float2*)(C + (size_t)(gr + 8) * TN + gc) = make_float2(acc[mt][nt][2], acc[mt][nt][3]);
        }
    }
}

// ---------------------------------------------------------------------------
// Depthwise 3x3 v3: zero-padded smem tile, 4 pixels/thread, float4 I/O
// ---------------------------------------------------------------------------
__global__ __launch_bounds__(256)
void dwconv3(const float* __restrict__ in, const float* __restrict__ wdw,
             float* __restrict__ out, float* __restrict__ norm2) {
    const int y0 = blockIdx.x * 32;
    const int ch = blockIdx.y;
    const int b  = blockIdx.z;
    const float* base = in + ((size_t)b * C3 + ch) * HW;
    float* obase = out + ((size_t)b * C3 + ch) * HW;

    __shared__ float t[34][136];   // data cols [4..131]; col 3 / col 132 zero

    if (threadIdx.x < 34) {
        t[threadIdx.x][3]   = 0.f;
        t[threadIdx.x][132] = 0.f;
    }
    for (int i = threadIdx.x; i < 34 * 32; i += 256) {
        int r = i >> 5, j = i & 31;
        int gy = y0 - 1 + r;
        float4 v = make_float4(0.f, 0.f, 0.f, 0.f);
        if (gy >= 0 && gy < HH) v = *(const float4*)(base + gy * WW + 4 * j);
        *(float4*)&t[r][4 + 4 * j] = v;
    }
    __syncthreads();

    float w[9];
#pragma unroll
    for (int i = 0; i < 9; i++) w[i] = wdw[ch * 9 + i];

    const int ry = threadIdx.x >> 5;
    const int x0 = (threadIdx.x & 31) << 2;
    const int c  = 4 + x0;

    float ss = 0.f;
#pragma unroll
    for (int jj = 0; jj < 4; jj++) {
        int y = ry * 4 + jj;
        float4 o = make_float4(0.f, 0.f, 0.f, 0.f);
#pragma unroll
        for (int dy = 0; dy < 3; dy++) {
            const float* rr = t[y + dy];
            float4 v = *(const float4*)&rr[c];
            float  l = rr[c - 1];
            float  rg = rr[c + 4];
            float w0 = w[dy * 3 + 0], w1 = w[dy * 3 + 1], w2 = w[dy * 3 + 2];
            o.x += l   * w0 + v.x * w1 + v.y * w2;
            o.y += v.x * w0 + v.y * w1 + v.z * w2;
            o.z += v.y * w0 + v.z * w1 + v.w * w2;
            o.w += v.z * w0 + v.w * w1 + rg  * w2;
        }
        *(float4*)(obase + (y0 + y) * WW + x0) = o;
        ss += o.x * o.x + o.y * o.y + o.z * o.z + o.w * o.w;
    }

    if (ch < 2 * CC) {
#pragma unroll
        for (int off = 16; off > 0; off >>= 1)
            ss += __shfl_down_sync(0xffffffffu, ss, off);
        __shared__ float wsum[8];
        if ((threadIdx.x & 31) == 0) wsum[threadIdx.x >> 5] = ss;
        __syncthreads();
        if (threadIdx.x == 0) {
            float tsum = 0.f;
#pragma unroll
            for (int i = 0; i < 8; i++) tsum += wsum[i];
            int idx;
            if (ch < CC) idx = (b * HEADS + ch / HD) * (2 * HD) + (ch % HD);
            else { int c2 = ch - CC; idx = (b * HEADS + c2 / HD) * (2 * HD) + HD + (c2 % HD); }
            atomicAdd(&norm2[idx], tsum);
        }
    }
}

// ---------------------------------------------------------------------------
// Gram: S[bh][i][j] += sum_p Q[i,p]*K[j,p]   (split-K, atomics)
// ---------------------------------------------------------------------------
__global__ __launch_bounds__(256)
void gram_kernel(const float* __restrict__ qkvd, float* __restrict__ S) {
    const int bh    = blockIdx.x;
    const int split = blockIdx.y;
    const int b = bh / HEADS, h = bh % HEADS;

    const float* Q  = qkvd + ((size_t)b * C3 + h * HD) * HW;
    const float* Kp = qkvd + ((size_t)b * C3 + CC + h * HD) * HW;

    __shared__ float Qs[48][33];
    __shared__ float Ks[48][33];

    const int tx = threadIdx.x & 15;
    const int ty = threadIdx.x >> 4;

    float acc[3][3];
#pragma unroll
    for (int i = 0; i < 3; i++)
#pragma unroll
        for (int j = 0; j < 3; j++) acc[i][j] = 0.f;

    const int p0 = split * (HW / 16);
    for (int pc = p0; pc < p0 + (HW / 16); pc += 32) {
        __syncthreads();
        for (int i = threadIdx.x; i < 48 * 32; i += 256) {
            int r = i >> 5, c = i & 31;
            Qs[r][c] = Q[(size_t)r * HW + pc + c];
            Ks[r][c] = Kp[(size_t)r * HW + pc + c];
        }
        __syncthreads();
#pragma unroll 8
        for (int kk = 0; kk < 32; kk++) {
            float a0 = Qs[ty * 3 + 0][kk];
            float a1 = Qs[ty * 3 + 1][kk];
            float a2 = Qs[ty * 3 + 2][kk];
            float b0 = Ks[tx * 3 + 0][kk];
            float b1 = Ks[tx * 3 + 1][kk];
            float b2 = Ks[tx * 3 + 2][kk];
            acc[0][0] += a0 * b0; acc[0][1] += a0 * b1; acc[0][2] += a0 * b2;
            acc[1][0] += a1 * b0; acc[1][1] += a1 * b1; acc[1][2] += a1 * b2;
            acc[2][0] += a2 * b0; acc[2][1] += a2 * b1; acc[2][2] += a2 * b2;
        }
    }

#pragma unroll
    for (int i = 0; i < 3; i++)
#pragma unroll
        for (int j = 0; j < 3; j++)
            atomicAdd(&S[((size_t)bh * HD + ty * 3 + i) * HD + tx * 3 + j], acc[i][j]);
}

// ---------------------------------------------------------------------------
// Softmax (48 wide) with L2-norm scaling + temperature
// ---------------------------------------------------------------------------
__global__ __launch_bounds__(48)
void softmax_kernel(float* __restrict__ S, const float* __restrict__ norm2,
                    const float* __restrict__ temperature) {
    const int bh = blockIdx.x;
    const int h  = bh % HEADS;
    const int i  = threadIdx.x;

    __shared__ float nk[48];
    const float* n2 = norm2 + bh * (2 * HD);
    nk[i] = fmaxf(sqrtf(n2[HD + i]), 1e-12f);
    __syncthreads();

    float nq = fmaxf(sqrtf(n2[i]), 1e-12f);
    float t  = temperature[h];

    float row[48];
    float mx = -1e30f;
    float* Srow = S + ((size_t)bh * HD + i) * HD;
#pragma unroll
    for (int j = 0; j < HD; j++) {
        row[j] = Srow[j] / (nq * nk[j]) * t;
        mx = fmaxf(mx, row[j]);
    }
    float sum = 0.f;
#pragma unroll
    for (int j = 0; j < HD; j++) {
        row[j] = expf(row[j] - mx);
        sum += row[j];
    }
    float inv = 1.f / sum;
#pragma unroll
    for (int j = 0; j < HD; j++) Srow[j] = row[j] * inv;
}

// ---------------------------------------------------------------------------
// M[b] = Wproj @ blockdiag(attn[b])
// ---------------------------------------------------------------------------
__global__ __launch_bounds__(256)
void build_M_kernel(const float* __restrict__ Wp, const float* __restrict__ attn,
                    float* __restrict__ Mm) {
    const int b = blockIdx.x;
    for (int idx = threadIdx.x; idx < CC * CC; idx += blockDim.x) {
        int o = idx / CC, d = idx % CC;
        int h = d / HD, dl = d % HD;
        const float* wrow = Wp + o * CC + h * HD;
        const float* acol = attn + ((size_t)(b * HEADS + h) * HD) * HD + dl;
        float s = 0.f;
#pragma unroll
        for (int cl = 0; cl < HD; cl++)
            s += wrow[cl] * acol[(size_t)cl * HD];
        Mm[(size_t)b * CC * CC + idx] = s;
    }
}

// ---------------------------------------------------------------------------
// Launch
// ---------------------------------------------------------------------------
extern "C" void kernel_launch(void* const* d_in, const int* in_sizes, int n_in,
                              void* d_out, int out_size) {
    const float* x     = (const float*)d_in[0];
    const float* wqkv  = (const float*)d_in[1];
    const float* wdw   = (const float*)d_in[2];
    const float* wproj = (const float*)d_in[3];
    const float* temp  = (const float*)d_in[4];
    float* out = (float*)d_out;

    float *qkv_p, *qkvd_p, *S_p, *n2_p, *M_p;
    cudaGetSymbolAddress((void**)&qkv_p,  g_qkv);
    cudaGetSymbolAddress((void**)&qkvd_p, g_qkvd);
    cudaGetSymbolAddress((void**)&S_p,    g_S);
    cudaGetSymbolAddress((void**)&n2_p,   g_n2);
    cudaGetSymbolAddress((void**)&M_p,    g_M);

    cudaFuncSetAttribute(gemm_tc, cudaFuncAttributeMaxDynamicSharedMemorySize, SMEM_GEMM);

    // 0. zero accumulators
    {
        int nS = BB * HEADS * HD * HD;
        int nN = BB * HEADS * 2 * HD;
        zero_kernel<<<(nS + 255) / 256, 256>>>(S_p, nS);
        zero_kernel<<<(nN + 255) / 256, 256>>>(n2_p, nN);
    }

    // 1. qkv = Wqkv @ x   (576 x 192 x 16384, tf32 tensor cores)
    {
        dim3 grid((C3 + GBM - 1) / GBM, TN / GBN, BB);   // M fastest
        gemm_tc<<<grid, 256, SMEM_GEMM>>>(wqkv, x, qkv_p, C3, CC,
                                          0, (size_t)CC * HW, (size_t)C3 * HW);
    }

    // 2. depthwise 3x3 + q/k norm accumulation (tiled, vectorized)
    {
        dim3 grid(HH / 32, C3, BB);
        dwconv3<<<grid, 256>>>(qkv_p, wdw, qkvd_p, n2_p);
    }

    // 3. Gram matrices
    {
        dim3 grid(BB * HEADS, 16);
        gram_kernel<<<grid, 256>>>(qkvd_p, S_p);
    }

    // 4. softmax
    softmax_kernel<<<BB * HEADS, 48>>>(S_p, n2_p, temp);

    // 5. M = Wproj @ blockdiag(attn)
    build_M_kernel<<<BB, 256>>>(wproj, S_p, M_p);

    // 6. out = M @ v   (192 x 192 x 16384, tf32 tensor cores)
    {
        dim3 grid((CC + GBM - 1) / GBM, TN / GBN, BB);   // M fastest
        gemm_tc<<<grid, 256, SMEM_GEMM>>>(M_p, qkvd_p + (size_t)2 * CC * HW, out, CC, CC,
                                          (size_t)CC * CC, (size_t)C3 * HW, (size_t)CC * HW);
    }
}

// round 9
// speedup vs baseline: 2.6338x; 1.2194x over previous
#include <cuda_runtime.h>
#include <cuda_fp16.h>
#include <math.h>
#include <stdint.h>

// Problem constants
#define BB   16
#define CC   192
#define HH   128
#define WW   128
#define HW   16384
#define C3   576
#define HEADS 4
#define HD   48
#define TN   16384

// ---------------------------------------------------------------------------
// Scratch
// ---------------------------------------------------------------------------
__device__ float g_qkv [(size_t)BB * C3 * HW];
__device__ float g_qkvd[(size_t)BB * C3 * HW];
__device__ float g_S   [BB * HEADS * HD * HD];
__device__ float g_n2  [BB * HEADS * 2 * HD];
__device__ float g_M   [BB * CC * CC];

__global__ void zero2_kernel(float* a, int na, float* b, int nb) {
    int i = blockIdx.x * blockDim.x + threadIdx.x;
    if (i < na) a[i] = 0.f;
    if (i < nb) b[i] = 0.f;
}

// ---------------------------------------------------------------------------
// fp16 tensor-core GEMM: C[M x 16384] = A[M x K] * B[K x 16384]
// (fp16 mantissa == tf32 mantissa -> same rounding as the tf32 version)
// 128x128 tile, BK=32, 256 threads, 8 warps (2x4), warp tile 64x32.
// ldmatrix fragment loads, m16n8k16 f16 MMA, fp32 accum, reg-prefetch
// double buffer.
// ---------------------------------------------------------------------------
#define GBM 128
#define GBN 128
#define GBK 32
#define APITCH 40     // halves per A row (80B, 16B-aligned, conflict-free)
#define BPITCH 136    // halves per B row (272B, 16B-aligned, conflict-free)

__device__ __forceinline__ void mma_f16(float* c, const unsigned* a, const unsigned* b) {
    asm volatile(
        "mma.sync.aligned.m16n8k16.row.col.f32.f16.f16.f32 "
        "{%0,%1,%2,%3}, {%4,%5,%6,%7}, {%8,%9}, {%0,%1,%2,%3};"
        : "+f"(c[0]), "+f"(c[1]), "+f"(c[2]), "+f"(c[3])
        : "r"(a[0]), "r"(a[1]), "r"(a[2]), "r"(a[3]), "r"(b[0]), "r"(b[1]));
}

__device__ __forceinline__ void ldsm_x4(unsigned* r, uint32_t addr) {
    asm volatile("ldmatrix.sync.aligned.m8n8.x4.shared.b16 {%0,%1,%2,%3}, [%4];"
                 : "=r"(r[0]), "=r"(r[1]), "=r"(r[2]), "=r"(r[3]) : "r"(addr));
}
__device__ __forceinline__ void ldsm_x2_t(unsigned* r, uint32_t addr) {
    asm volatile("ldmatrix.sync.aligned.m8n8.x2.trans.shared.b16 {%0,%1}, [%2];"
                 : "=r"(r[0]), "=r"(r[1]) : "r"(addr));
}

__global__ __launch_bounds__(256)
void gemm_fp16(const float* __restrict__ Ag, const float* __restrict__ Bg,
               float* __restrict__ Cg, int M, int K,
               size_t sA, size_t sB, size_t sC) {
    __shared__ __half As[2][GBM][APITCH];
    __shared__ __half Bs[2][GBK][BPITCH];

    Ag += (size_t)blockIdx.z * sA;
    Bg += (size_t)blockIdx.z * sB;
    Cg += (size_t)blockIdx.z * sC;
    const int m0 = blockIdx.x * GBM;
    const int n0 = blockIdx.y * GBN;
    const int tid = threadIdx.x;
    const int warp = tid >> 5, lane = tid & 31;
    const int wm = (warp >> 2) * 64;
    const int wn = (warp & 3) * 32;

    float acc[4][4][4];
#pragma unroll
    for (int i = 0; i < 4; i++)
#pragma unroll
        for (int j = 0; j < 4; j++)
#pragma unroll
            for (int l = 0; l < 4; l++) acc[i][j][l] = 0.f;

    const int NK = K / GBK;          // 6
    float4 pa[4], pb[4];

    auto prefetch = [&](int it) {
        const int k0 = it * GBK;
#pragma unroll
        for (int i = 0; i < 4; i++) {
            int idx = tid + i * 256;             // A: 1024 float4 (128 x 32)
            int row = idx >> 3, kq = (idx & 7) << 2;
            int r = m0 + row; if (r >= M) r = M - 1;
            pa[i] = *(const float4*)(Ag + (size_t)r * K + k0 + kq);
        }
#pragma unroll
        for (int i = 0; i < 4; i++) {
            int idx = tid + i * 256;             // B: 1024 float4 (32 x 128)
            int k = idx >> 5, nq = (idx & 31) << 2;
            pb[i] = *(const float4*)(Bg + (size_t)(k0 + k) * TN + n0 + nq);
        }
    };

    prefetch(0);

    const uint32_t aBase = (uint32_t)__cvta_generic_to_shared(&As[0][0][0]);
    const uint32_t bBase = (uint32_t)__cvta_generic_to_shared(&Bs[0][0][0]);
    const uint32_t aBufB = GBM * APITCH * 2;     // bytes per A buffer
    const uint32_t bBufB = GBK * BPITCH * 2;

    // per-lane ldmatrix address components
    const int arow = wm + (lane & 15);           // + mt*16
    const int acolh = (lane >> 4) << 3;          // 0 or 8 (k half)
    const int brow = lane & 15;                  // + ks

    for (int it = 0; it < NK; it++) {
        const int buf = it & 1;
        // store prefetched tile (convert fp32 -> fp16)
#pragma unroll
        for (int i = 0; i < 4; i++) {
            int idx = tid + i * 256;
            int row = idx >> 3, kq = (idx & 7) << 2;
            __half2* p = (__half2*)&As[buf][row][kq];
            p[0] = __floats2half2_rn(pa[i].x, pa[i].y);
            p[1] = __floats2half2_rn(pa[i].z, pa[i].w);
        }
#pragma unroll
        for (int i = 0; i < 4; i++) {
            int idx = tid + i * 256;
            int k = idx >> 5, nq = (idx & 31) << 2;
            __half2* p = (__half2*)&Bs[buf][k][nq];
            p[0] = __floats2half2_rn(pb[i].x, pb[i].y);
            p[1] = __floats2half2_rn(pb[i].z, pb[i].w);
        }
        __syncthreads();

        if (it + 1 < NK) prefetch(it + 1);

        const uint32_t aB = aBase + buf * aBufB;
        const uint32_t bB = bBase + buf * bBufB;
#pragma unroll
        for (int ks = 0; ks < GBK; ks += 16) {
            unsigned af[4][4];
#pragma unroll
            for (int mt = 0; mt < 4; mt++)
                ldsm_x4(af[mt], aB + ((arow + mt * 16) * APITCH + ks + acolh) * 2);
            unsigned bf[4][2];
#pragma unroll
            for (int nt = 0; nt < 4; nt++)
                ldsm_x2_t(bf[nt], bB + ((ks + brow) * BPITCH + wn + nt * 8) * 2);
#pragma unroll
            for (int mt = 0; mt < 4; mt++)
#pragma unroll
                for (int nt = 0; nt < 4; nt++)
                    mma_f16(acc[mt][nt], af[mt], bf[nt]);
        }
        __syncthreads();
    }

    // epilogue
    const int frow = lane >> 2;
    const int qc = (lane & 3) * 2;
#pragma unroll
    for (int mt = 0; mt < 4; mt++) {
        int gr = m0 + wm + mt * 16 + frow;
#pragma unroll
        for (int nt = 0; nt < 4; nt++) {
            int gc = n0 + wn + nt * 8 + qc;
            if (gr < M)
                *(float2*)(Cg + (size_t)gr * TN + gc) = make_float2(acc[mt][nt][0], acc[mt][nt][1]);
            if (gr + 8 < M)
                *(float2*)(Cg + (size_t)(gr + 8) * TN + gc) = make_float2(acc[mt][nt][2], acc[mt][nt][3]);
        }
    }
}

// ---------------------------------------------------------------------------
// Depthwise 3x3: zero-padded smem tile, 4 pixels/thread, float4 I/O
// ---------------------------------------------------------------------------
__global__ __launch_bounds__(256)
void dwconv3(const float* __restrict__ in, const float* __restrict__ wdw,
             float* __restrict__ out, float* __restrict__ norm2) {
    const int y0 = blockIdx.x * 32;
    const int ch = blockIdx.y;
    const int b  = blockIdx.z;
    const float* base = in + ((size_t)b * C3 + ch) * HW;
    float* obase = out + ((size_t)b * C3 + ch) * HW;

    __shared__ float t[34][136];

    if (threadIdx.x < 34) {
        t[threadIdx.x][3]   = 0.f;
        t[threadIdx.x][132] = 0.f;
    }
    for (int i = threadIdx.x; i < 34 * 32; i += 256) {
        int r = i >> 5, j = i & 31;
        int gy = y0 - 1 + r;
        float4 v = make_float4(0.f, 0.f, 0.f, 0.f);
        if (gy >= 0 && gy < HH) v = *(const float4*)(base + gy * WW + 4 * j);
        *(float4*)&t[r][4 + 4 * j] = v;
    }
    __syncthreads();

    float w[9];
#pragma unroll
    for (int i = 0; i < 9; i++) w[i] = wdw[ch * 9 + i];

    const int ry = threadIdx.x >> 5;
    const int x0 = (threadIdx.x & 31) << 2;
    const int c  = 4 + x0;

    float ss = 0.f;
#pragma unroll
    for (int jj = 0; jj < 4; jj++) {
        int y = ry * 4 + jj;
        float4 o = make_float4(0.f, 0.f, 0.f, 0.f);
#pragma unroll
        for (int dy = 0; dy < 3; dy++) {
            const float* rr = t[y + dy];
            float4 v = *(const float4*)&rr[c];
            float  l = rr[c - 1];
            float  rg = rr[c + 4];
            float w0 = w[dy * 3 + 0], w1 = w[dy * 3 + 1], w2 = w[dy * 3 + 2];
            o.x += l   * w0 + v.x * w1 + v.y * w2;
            o.y += v.x * w0 + v.y * w1 + v.z * w2;
            o.z += v.y * w0 + v.z * w1 + v.w * w2;
            o.w += v.z * w0 + v.w * w1 + rg  * w2;
        }
        *(float4*)(obase + (y0 + y) * WW + x0) = o;
        ss += o.x * o.x + o.y * o.y + o.z * o.z + o.w * o.w;
    }

    if (ch < 2 * CC) {
#pragma unroll
        for (int off = 16; off > 0; off >>= 1)
            ss += __shfl_down_sync(0xffffffffu, ss, off);
        __shared__ float wsum[8];
        if ((threadIdx.x & 31) == 0) wsum[threadIdx.x >> 5] = ss;
        __syncthreads();
        if (threadIdx.x == 0) {
            float tsum = 0.f;
#pragma unroll
            for (int i = 0; i < 8; i++) tsum += wsum[i];
            int idx;
            if (ch < CC) idx = (b * HEADS + ch / HD) * (2 * HD) + (ch % HD);
            else { int c2 = ch - CC; idx = (b * HEADS + c2 / HD) * (2 * HD) + HD + (c2 % HD); }
            atomicAdd(&norm2[idx], tsum);
        }
    }
}

// ---------------------------------------------------------------------------
// Gram: S[bh][i][j] += sum_p Q[i,p]*K[j,p]   (split-K, atomics)
// ---------------------------------------------------------------------------
__global__ __launch_bounds__(256)
void gram_kernel(const float* __restrict__ qkvd, float* __restrict__ S) {
    const int bh    = blockIdx.x;
    const int split = blockIdx.y;
    const int b = bh / HEADS, h = bh % HEADS;

    const float* Q  = qkvd + ((size_t)b * C3 + h * HD) * HW;
    const float* Kp = qkvd + ((size_t)b * C3 + CC + h * HD) * HW;

    __shared__ float Qs[48][33];
    __shared__ float Ks[48][33];

    const int tx = threadIdx.x & 15;
    const int ty = threadIdx.x >> 4;

    float acc[3][3];
#pragma unroll
    for (int i = 0; i < 3; i++)
#pragma unroll
        for (int j = 0; j < 3; j++) acc[i][j] = 0.f;

    const int p0 = split * (HW / 16);
    for (int pc = p0; pc < p0 + (HW / 16); pc += 32) {
        __syncthreads();
        for (int i = threadIdx.x; i < 48 * 32; i += 256) {
            int r = i >> 5, c = i & 31;
            Qs[r][c] = Q[(size_t)r * HW + pc + c];
            Ks[r][c] = Kp[(size_t)r * HW + pc + c];
        }
        __syncthreads();
#pragma unroll 8
        for (int kk = 0; kk < 32; kk++) {
            float a0 = Qs[ty * 3 + 0][kk];
            float a1 = Qs[ty * 3 + 1][kk];
            float a2 = Qs[ty * 3 + 2][kk];
            float b0 = Ks[tx * 3 + 0][kk];
            float b1 = Ks[tx * 3 + 1][kk];
            float b2 = Ks[tx * 3 + 2][kk];
            acc[0][0] += a0 * b0; acc[0][1] += a0 * b1; acc[0][2] += a0 * b2;
            acc[1][0] += a1 * b0; acc[1][1] += a1 * b1; acc[1][2] += a1 * b2;
            acc[2][0] += a2 * b0; acc[2][1] += a2 * b1; acc[2][2] += a2 * b2;
        }
    }

#pragma unroll
    for (int i = 0; i < 3; i++)
#pragma unroll
        for (int j = 0; j < 3; j++)
            atomicAdd(&S[((size_t)bh * HD + ty * 3 + i) * HD + tx * 3 + j], acc[i][j]);
}

// ---------------------------------------------------------------------------
// Softmax (48) + M = Wproj @ blockdiag(attn), one block per batch
// ---------------------------------------------------------------------------
__global__ __launch_bounds__(256)
void softmax_M_kernel(float* __restrict__ S, const float* __restrict__ norm2,
                      const float* __restrict__ temperature,
                      const float* __restrict__ Wp, float* __restrict__ Mm) {
    const int b = blockIdx.x;
    const int t = threadIdx.x;

    if (t < HEADS * HD) {
        int h = t / HD, i = t % HD;
        int bh = b * HEADS + h;
        const float* n2 = norm2 + bh * (2 * HD);
        float nq = fmaxf(sqrtf(n2[i]), 1e-12f);
        float tv = temperature[h];
        float* Srow = S + ((size_t)bh * HD + i) * HD;

        float row[48];
        float mx = -1e30f;
#pragma unroll
        for (int j = 0; j < HD; j++) {
            float nk = fmaxf(sqrtf(n2[HD + j]), 1e-12f);
            row[j] = Srow[j] / (nq * nk) * tv;
            mx = fmaxf(mx, row[j]);
        }
        float sum = 0.f;
#pragma unroll
        for (int j = 0; j < HD; j++) {
            row[j] = expf(row[j] - mx);
            sum += row[j];
        }
        float inv = 1.f / sum;
#pragma unroll
        for (int j = 0; j < HD; j++) Srow[j] = row[j] * inv;
    }
    __syncthreads();

    const float* attn = S;
    for (int idx = t; idx < CC * CC; idx += blockDim.x) {
        int o = idx / CC, d = idx % CC;
        int h = d / HD, dl = d % HD;
        const float* wrow = Wp + o * CC + h * HD;
        const float* acol = attn + ((size_t)(b * HEADS + h) * HD) * HD + dl;
        float s = 0.f;
#pragma unroll
        for (int cl = 0; cl < HD; cl++)
            s += wrow[cl] * acol[(size_t)cl * HD];
        Mm[(size_t)b * CC * CC + idx] = s;
    }
}

// ---------------------------------------------------------------------------
// Launch
// ---------------------------------------------------------------------------
extern "C" void kernel_launch(void* const* d_in, const int* in_sizes, int n_in,
                              void* d_out, int out_size) {
    const float* x     = (const float*)d_in[0];
    const float* wqkv  = (const float*)d_in[1];
    const float* wdw   = (const float*)d_in[2];
    const float* wproj = (const float*)d_in[3];
    const float* temp  = (const float*)d_in[4];
    float* out = (float*)d_out;

    float *qkv_p, *qkvd_p, *S_p, *n2_p, *M_p;
    cudaGetSymbolAddress((void**)&qkv_p,  g_qkv);
    cudaGetSymbolAddress((void**)&qkvd_p, g_qkvd);
    cudaGetSymbolAddress((void**)&S_p,    g_S);
    cudaGetSymbolAddress((void**)&n2_p,   g_n2);
    cudaGetSymbolAddress((void**)&M_p,    g_M);

    // 1. zero accumulators
    {
        int nS = BB * HEADS * HD * HD;
        int nN = BB * HEADS * 2 * HD;
        zero2_kernel<<<(nS + 255) / 256, 256>>>(S_p, nS, n2_p, nN);
    }

    // 2. qkv = Wqkv @ x   (fp16 tensor cores, fp32 accum)
    {
        dim3 grid((C3 + GBM - 1) / GBM, TN / GBN, BB);
        gemm_fp16<<<grid, 256>>>(wqkv, x, qkv_p, C3, CC,
                                 0, (size_t)CC * HW, (size_t)C3 * HW);
    }

    // 3. depthwise 3x3 + q/k norm accumulation
    {
        dim3 grid(HH / 32, C3, BB);
        dwconv3<<<grid, 256>>>(qkv_p, wdw, qkvd_p, n2_p);
    }

    // 4. Gram matrices
    {
        dim3 grid(BB * HEADS, 16);
        gram_kernel<<<grid, 256>>>(qkvd_p, S_p);
    }

    // 5. softmax + M build
    softmax_M_kernel<<<BB, 256>>>(S_p, n2_p, temp, wproj, M_p);

    // 6. out = M @ v   (fp16 tensor cores, fp32 accum)
    {
        dim3 grid((CC + GBM - 1) / GBM, TN / GBN, BB);
        gemm_fp16<<<grid, 256>>>(M_p, qkvd_p + (size_t)2 * CC * HW, out, CC, CC,
                                 (size_t)CC * CC, (size_t)C3 * HW, (size_t)CC * HW);
    }
}

// round 10
// speedup vs baseline: 3.4144x; 1.2964x over previous
#include <cuda_runtime.h>
#include <cuda_fp16.h>
#include <math.h>
#include <stdint.h>

// Problem constants
#define BB   16
#define CC   192
#define HH   128
#define WW   128
#define HW   16384
#define C3   576
#define HEADS 4
#define HD   48
#define TN   16384
#define KSPLIT 8

// ---------------------------------------------------------------------------
// Scratch
// ---------------------------------------------------------------------------
__device__ float  g_qkv [(size_t)BB * C3 * HW];   // fp32 (pre-dwconv)
__device__ __half g_qkvd[(size_t)BB * C3 * HW];   // fp16 (post-dwconv)
__device__ float  g_S   [BB * HEADS * HD * HD];
__device__ float  g_n2  [BB * HEADS * 2 * HD];
__device__ float  g_M   [BB * CC * CC];

__global__ void zero2_kernel(float* a, int na, float* b, int nb) {
    int i = blockIdx.x * blockDim.x + threadIdx.x;
    if (i < na) a[i] = 0.f;
    if (i < nb) b[i] = 0.f;
}

// ---------------------------------------------------------------------------
// MMA / ldmatrix helpers
// ---------------------------------------------------------------------------
__device__ __forceinline__ void mma_f16(float* c, const unsigned* a, const unsigned* b) {
    asm volatile(
        "mma.sync.aligned.m16n8k16.row.col.f32.f16.f16.f32 "
        "{%0,%1,%2,%3}, {%4,%5,%6,%7}, {%8,%9}, {%0,%1,%2,%3};"
        : "+f"(c[0]), "+f"(c[1]), "+f"(c[2]), "+f"(c[3])
        : "r"(a[0]), "r"(a[1]), "r"(a[2]), "r"(a[3]), "r"(b[0]), "r"(b[1]));
}
__device__ __forceinline__ void ldsm_x4(unsigned* r, uint32_t addr) {
    asm volatile("ldmatrix.sync.aligned.m8n8.x4.shared.b16 {%0,%1,%2,%3}, [%4];"
                 : "=r"(r[0]), "=r"(r[1]), "=r"(r[2]), "=r"(r[3]) : "r"(addr));
}
__device__ __forceinline__ void ldsm_x2_t(unsigned* r, uint32_t addr) {
    asm volatile("ldmatrix.sync.aligned.m8n8.x2.trans.shared.b16 {%0,%1}, [%2];"
                 : "=r"(r[0]), "=r"(r[1]) : "r"(addr));
}

// ---------------------------------------------------------------------------
// fp16 TC GEMM (B fp32 in gmem): C[M x 16384] = A[M x K] * B[K x 16384]
// 128x128 tile, BK=32, 8 warps (2x4), warp 64x32, reg-prefetch double buffer
// ---------------------------------------------------------------------------
#define GBM 128
#define GBN 128
#define GBK 32
#define APITCH 40
#define BPITCH 136

__global__ __launch_bounds__(256)
void gemm_fp16(const float* __restrict__ Ag, const float* __restrict__ Bg,
               float* __restrict__ Cg, int M, int K,
               size_t sA, size_t sB, size_t sC) {
    __shared__ __half As[2][GBM][APITCH];
    __shared__ __half Bs[2][GBK][BPITCH];

    Ag += (size_t)blockIdx.z * sA;
    Bg += (size_t)blockIdx.z * sB;
    Cg += (size_t)blockIdx.z * sC;
    const int m0 = blockIdx.x * GBM;
    const int n0 = blockIdx.y * GBN;
    const int tid = threadIdx.x;
    const int warp = tid >> 5, lane = tid & 31;
    const int wm = (warp >> 2) * 64;
    const int wn = (warp & 3) * 32;

    float acc[4][4][4];
#pragma unroll
    for (int i = 0; i < 4; i++)
#pragma unroll
        for (int j = 0; j < 4; j++)
#pragma unroll
            for (int l = 0; l < 4; l++) acc[i][j][l] = 0.f;

    const int NK = K / GBK;
    float4 pa[4], pb[4];

    auto prefetch = [&](int it) {
        const int k0 = it * GBK;
#pragma unroll
        for (int i = 0; i < 4; i++) {
            int idx = tid + i * 256;
            int row = idx >> 3, kq = (idx & 7) << 2;
            int r = m0 + row; if (r >= M) r = M - 1;
            pa[i] = *(const float4*)(Ag + (size_t)r * K + k0 + kq);
        }
#pragma unroll
        for (int i = 0; i < 4; i++) {
            int idx = tid + i * 256;
            int k = idx >> 5, nq = (idx & 31) << 2;
            pb[i] = *(const float4*)(Bg + (size_t)(k0 + k) * TN + n0 + nq);
        }
    };

    prefetch(0);

    const uint32_t aBase = (uint32_t)__cvta_generic_to_shared(&As[0][0][0]);
    const uint32_t bBase = (uint32_t)__cvta_generic_to_shared(&Bs[0][0][0]);
    const uint32_t aBufB = GBM * APITCH * 2;
    const uint32_t bBufB = GBK * BPITCH * 2;

    const int arow = wm + (lane & 15);
    const int acolh = (lane >> 4) << 3;
    const int brow = lane & 15;

    for (int it = 0; it < NK; it++) {
        const int buf = it & 1;
#pragma unroll
        for (int i = 0; i < 4; i++) {
            int idx = tid + i * 256;
            int row = idx >> 3, kq = (idx & 7) << 2;
            __half2* p = (__half2*)&As[buf][row][kq];
            p[0] = __floats2half2_rn(pa[i].x, pa[i].y);
            p[1] = __floats2half2_rn(pa[i].z, pa[i].w);
        }
#pragma unroll
        for (int i = 0; i < 4; i++) {
            int idx = tid + i * 256;
            int k = idx >> 5, nq = (idx & 31) << 2;
            __half2* p = (__half2*)&Bs[buf][k][nq];
            p[0] = __floats2half2_rn(pb[i].x, pb[i].y);
            p[1] = __floats2half2_rn(pb[i].z, pb[i].w);
        }
        __syncthreads();

        if (it + 1 < NK) prefetch(it + 1);

        const uint32_t aB = aBase + buf * aBufB;
        const uint32_t bB = bBase + buf * bBufB;
#pragma unroll
        for (int ks = 0; ks < GBK; ks += 16) {
            unsigned af[4][4];
#pragma unroll
            for (int mt = 0; mt < 4; mt++)
                ldsm_x4(af[mt], aB + ((arow + mt * 16) * APITCH + ks + acolh) * 2);
            unsigned bf[4][2];
#pragma unroll
            for (int nt = 0; nt < 4; nt++)
                ldsm_x2_t(bf[nt], bB + ((ks + brow) * BPITCH + wn + nt * 8) * 2);
#pragma unroll
            for (int mt = 0; mt < 4; mt++)
#pragma unroll
                for (int nt = 0; nt < 4; nt++)
                    mma_f16(acc[mt][nt], af[mt], bf[nt]);
        }
        __syncthreads();
    }

    const int frow = lane >> 2;
    const int qc = (lane & 3) * 2;
#pragma unroll
    for (int mt = 0; mt < 4; mt++) {
        int gr = m0 + wm + mt * 16 + frow;
#pragma unroll
        for (int nt = 0; nt < 4; nt++) {
            int gc = n0 + wn + nt * 8 + qc;
            if (gr < M)
                *(float2*)(Cg + (size_t)gr * TN + gc) = make_float2(acc[mt][nt][0], acc[mt][nt][1]);
            if (gr + 8 < M)
                *(float2*)(Cg + (size_t)(gr + 8) * TN + gc) = make_float2(acc[mt][nt][2], acc[mt][nt][3]);
        }
    }
}

// ---------------------------------------------------------------------------
// fp16 TC GEMM, B already fp16 in gmem. Same structure.
// ---------------------------------------------------------------------------
__global__ __launch_bounds__(256)
void gemm_fp16h(const float* __restrict__ Ag, const __half* __restrict__ Bg,
                float* __restrict__ Cg, int M, int K,
                size_t sA, size_t sB, size_t sC) {
    __shared__ __half As[2][GBM][APITCH];
    __shared__ __half Bs[2][GBK][BPITCH];

    Ag += (size_t)blockIdx.z * sA;
    Bg += (size_t)blockIdx.z * sB;
    Cg += (size_t)blockIdx.z * sC;
    const int m0 = blockIdx.x * GBM;
    const int n0 = blockIdx.y * GBN;
    const int tid = threadIdx.x;
    const int warp = tid >> 5, lane = tid & 31;
    const int wm = (warp >> 2) * 64;
    const int wn = (warp & 3) * 32;

    float acc[4][4][4];
#pragma unroll
    for (int i = 0; i < 4; i++)
#pragma unroll
        for (int j = 0; j < 4; j++)
#pragma unroll
            for (int l = 0; l < 4; l++) acc[i][j][l] = 0.f;

    const int NK = K / GBK;
    float4 pa[4];
    uint4  pb[2];

    auto prefetch = [&](int it) {
        const int k0 = it * GBK;
#pragma unroll
        for (int i = 0; i < 4; i++) {
            int idx = tid + i * 256;
            int row = idx >> 3, kq = (idx & 7) << 2;
            int r = m0 + row; if (r >= M) r = M - 1;
            pa[i] = *(const float4*)(Ag + (size_t)r * K + k0 + kq);
        }
#pragma unroll
        for (int i = 0; i < 2; i++) {
            int idx = tid + i * 256;              // 512 x uint4 (8 halves)
            int k = idx >> 4, nq8 = (idx & 15) << 3;
            pb[i] = *(const uint4*)(Bg + (size_t)(k0 + k) * TN + n0 + nq8);
        }
    };

    prefetch(0);

    const uint32_t aBase = (uint32_t)__cvta_generic_to_shared(&As[0][0][0]);
    const uint32_t bBase = (uint32_t)__cvta_generic_to_shared(&Bs[0][0][0]);
    const uint32_t aBufB = GBM * APITCH * 2;
    const uint32_t bBufB = GBK * BPITCH * 2;

    const int arow = wm + (lane & 15);
    const int acolh = (lane >> 4) << 3;
    const int brow = lane & 15;

    for (int it = 0; it < NK; it++) {
        const int buf = it & 1;
#pragma unroll
        for (int i = 0; i < 4; i++) {
            int idx = tid + i * 256;
            int row = idx >> 3, kq = (idx & 7) << 2;
            __half2* p = (__half2*)&As[buf][row][kq];
            p[0] = __floats2half2_rn(pa[i].x, pa[i].y);
            p[1] = __floats2half2_rn(pa[i].z, pa[i].w);
        }
#pragma unroll
        for (int i = 0; i < 2; i++) {
            int idx = tid + i * 256;
            int k = idx >> 4, nq8 = (idx & 15) << 3;
            *(uint4*)&Bs[buf][k][nq8] = pb[i];
        }
        __syncthreads();

        if (it + 1 < NK) prefetch(it + 1);

        const uint32_t aB = aBase + buf * aBufB;
        const uint32_t bB = bBase + buf * bBufB;
#pragma unroll
        for (int ks = 0; ks < GBK; ks += 16) {
            unsigned af[4][4];
#pragma unroll
            for (int mt = 0; mt < 4; mt++)
                ldsm_x4(af[mt], aB + ((arow + mt * 16) * APITCH + ks + acolh) * 2);
            unsigned bf[4][2];
#pragma unroll
            for (int nt = 0; nt < 4; nt++)
                ldsm_x2_t(bf[nt], bB + ((ks + brow) * BPITCH + wn + nt * 8) * 2);
#pragma unroll
            for (int mt = 0; mt < 4; mt++)
#pragma unroll
                for (int nt = 0; nt < 4; nt++)
                    mma_f16(acc[mt][nt], af[mt], bf[nt]);
        }
        __syncthreads();
    }

    const int frow = lane >> 2;
    const int qc = (lane & 3) * 2;
#pragma unroll
    for (int mt = 0; mt < 4; mt++) {
        int gr = m0 + wm + mt * 16 + frow;
#pragma unroll
        for (int nt = 0; nt < 4; nt++) {
            int gc = n0 + wn + nt * 8 + qc;
            if (gr < M)
                *(float2*)(Cg + (size_t)gr * TN + gc) = make_float2(acc[mt][nt][0], acc[mt][nt][1]);
            if (gr + 8 < M)
                *(float2*)(Cg + (size_t)(gr + 8) * TN + gc) = make_float2(acc[mt][nt][2], acc[mt][nt][3]);
        }
    }
}

// ---------------------------------------------------------------------------
// Depthwise 3x3 -> fp16 output + fp32 norms (of the rounded values)
// ---------------------------------------------------------------------------
__global__ __launch_bounds__(256)
void dwconv3h(const float* __restrict__ in, const float* __restrict__ wdw,
              __half* __restrict__ out, float* __restrict__ norm2) {
    const int y0 = blockIdx.x * 32;
    const int ch = blockIdx.y;
    const int b  = blockIdx.z;
    const float* base = in + ((size_t)b * C3 + ch) * HW;
    __half* obase = out + ((size_t)b * C3 + ch) * HW;

    __shared__ float t[34][136];

    if (threadIdx.x < 34) {
        t[threadIdx.x][3]   = 0.f;
        t[threadIdx.x][132] = 0.f;
    }
    for (int i = threadIdx.x; i < 34 * 32; i += 256) {
        int r = i >> 5, j = i & 31;
        int gy = y0 - 1 + r;
        float4 v = make_float4(0.f, 0.f, 0.f, 0.f);
        if (gy >= 0 && gy < HH) v = *(const float4*)(base + gy * WW + 4 * j);
        *(float4*)&t[r][4 + 4 * j] = v;
    }
    __syncthreads();

    float w[9];
#pragma unroll
    for (int i = 0; i < 9; i++) w[i] = wdw[ch * 9 + i];

    const int ry = threadIdx.x >> 5;
    const int x0 = (threadIdx.x & 31) << 2;
    const int c  = 4 + x0;

    float ss = 0.f;
#pragma unroll
    for (int jj = 0; jj < 4; jj++) {
        int y = ry * 4 + jj;
        float4 o = make_float4(0.f, 0.f, 0.f, 0.f);
#pragma unroll
        for (int dy = 0; dy < 3; dy++) {
            const float* rr = t[y + dy];
            float4 v = *(const float4*)&rr[c];
            float  l = rr[c - 1];
            float  rg = rr[c + 4];
            float w0 = w[dy * 3 + 0], w1 = w[dy * 3 + 1], w2 = w[dy * 3 + 2];
            o.x += l   * w0 + v.x * w1 + v.y * w2;
            o.y += v.x * w0 + v.y * w1 + v.z * w2;
            o.z += v.y * w0 + v.z * w1 + v.w * w2;
            o.w += v.z * w0 + v.w * w1 + rg  * w2;
        }
        __half2 h01 = __floats2half2_rn(o.x, o.y);
        __half2 h23 = __floats2half2_rn(o.z, o.w);
        *(__half2*)(obase + (y0 + y) * WW + x0)     = h01;
        *(__half2*)(obase + (y0 + y) * WW + x0 + 2) = h23;
        float r0 = __low2float(h01), r1 = __high2float(h01);
        float r2 = __low2float(h23), r3 = __high2float(h23);
        ss += r0 * r0 + r1 * r1 + r2 * r2 + r3 * r3;
    }

    if (ch < 2 * CC) {
#pragma unroll
        for (int off = 16; off > 0; off >>= 1)
            ss += __shfl_down_sync(0xffffffffu, ss, off);
        __shared__ float wsum[8];
        if ((threadIdx.x & 31) == 0) wsum[threadIdx.x >> 5] = ss;
        __syncthreads();
        if (threadIdx.x == 0) {
            float tsum = 0.f;
#pragma unroll
            for (int i = 0; i < 8; i++) tsum += wsum[i];
            int idx;
            if (ch < CC) idx = (b * HEADS + ch / HD) * (2 * HD) + (ch % HD);
            else { int c2 = ch - CC; idx = (b * HEADS + c2 / HD) * (2 * HD) + HD + (c2 % HD); }
            atomicAdd(&norm2[idx], tsum);
        }
    }
}

// ---------------------------------------------------------------------------
// Gram via fp16 MMA, fragments loaded directly from gmem.
// grid = (64 bh, KSPLIT); block = 256 (8 warps). Each warp: full 48x48,
// k-slice of 16384/(KSPLIT*8). smem reduction, then global atomicAdd.
// ---------------------------------------------------------------------------
__global__ __launch_bounds__(256)
void gram_mma(const __half* __restrict__ qkvd, float* __restrict__ S) {
    const int bh = blockIdx.x;
    const int b = bh / HEADS, h = bh % HEADS;
    const __half* Q  = qkvd + ((size_t)b * C3 + h * HD) * HW;
    const __half* Kp = qkvd + ((size_t)b * C3 + CC + h * HD) * HW;

    __shared__ float Ssh[HD * HD];
    for (int i = threadIdx.x; i < HD * HD; i += 256) Ssh[i] = 0.f;
    __syncthreads();

    const int warp = threadIdx.x >> 5, lane = threadIdx.x & 31;
    const int g  = lane >> 2;          // 0..7
    const int cq = (lane & 3) << 1;    // 0,2,4,6

    const int span = HW / (KSPLIT * 8);            // 256
    const int pc0 = (blockIdx.y * 8 + warp) * span;

    float acc[3][6][4];
#pragma unroll
    for (int i = 0; i < 3; i++)
#pragma unroll
        for (int j = 0; j < 6; j++)
#pragma unroll
            for (int l = 0; l < 4; l++) acc[i][j][l] = 0.f;

    for (int pc = pc0; pc < pc0 + span; pc += 16) {
        unsigned af[3][4], bf[6][2];
#pragma unroll
        for (int mt = 0; mt < 3; mt++) {
            const __half* qr = Q + (size_t)(mt * 16 + g) * HW + pc + cq;
            af[mt][0] = *(const unsigned*)(qr);
            af[mt][1] = *(const unsigned*)(qr + 8 * HW);
            af[mt][2] = *(const unsigned*)(qr + 8);
            af[mt][3] = *(const unsigned*)(qr + 8 * HW + 8);
        }
#pragma unroll
        for (int nt = 0; nt < 6; nt++) {
            const __half* kr = Kp + (size_t)(nt * 8 + g) * HW + pc + cq;
            bf[nt][0] = *(const unsigned*)(kr);
            bf[nt][1] = *(const unsigned*)(kr + 8);
        }
#pragma unroll
        for (int mt = 0; mt < 3; mt++)
#pragma unroll
            for (int nt = 0; nt < 6; nt++)
                mma_f16(acc[mt][nt], af[mt], bf[nt]);
    }

    // reduce into smem
#pragma unroll
    for (int mt = 0; mt < 3; mt++) {
#pragma unroll
        for (int nt = 0; nt < 6; nt++) {
            int r0 = mt * 16 + g;
            int c0 = nt * 8 + cq;
            atomicAdd(&Ssh[r0 * HD + c0],           acc[mt][nt][0]);
            atomicAdd(&Ssh[r0 * HD + c0 + 1],       acc[mt][nt][1]);
            atomicAdd(&Ssh[(r0 + 8) * HD + c0],     acc[mt][nt][2]);
            atomicAdd(&Ssh[(r0 + 8) * HD + c0 + 1], acc[mt][nt][3]);
        }
    }
    __syncthreads();

    float* Sg = S + (size_t)bh * HD * HD;
    for (int i = threadIdx.x; i < HD * HD; i += 256)
        atomicAdd(&Sg[i], Ssh[i]);
}

// ---------------------------------------------------------------------------
// Softmax (48) + M = Wproj @ blockdiag(attn), one block per batch
// ---------------------------------------------------------------------------
__global__ __launch_bounds__(256)
void softmax_M_kernel(float* __restrict__ S, const float* __restrict__ norm2,
                      const float* __restrict__ temperature,
                      const float* __restrict__ Wp, float* __restrict__ Mm) {
    const int b = blockIdx.x;
    const int t = threadIdx.x;

    if (t < HEADS * HD) {
        int h = t / HD, i = t % HD;
        int bh = b * HEADS + h;
        const float* n2 = norm2 + bh * (2 * HD);
        float nq = fmaxf(sqrtf(n2[i]), 1e-12f);
        float tv = temperature[h];
        float* Srow = S + ((size_t)bh * HD + i) * HD;

        float row[48];
        float mx = -1e30f;
#pragma unroll
        for (int j = 0; j < HD; j++) {
            float nk = fmaxf(sqrtf(n2[HD + j]), 1e-12f);
            row[j] = Srow[j] / (nq * nk) * tv;
            mx = fmaxf(mx, row[j]);
        }
        float sum = 0.f;
#pragma unroll
        for (int j = 0; j < HD; j++) {
            row[j] = expf(row[j] - mx);
            sum += row[j];
        }
        float inv = 1.f / sum;
#pragma unroll
        for (int j = 0; j < HD; j++) Srow[j] = row[j] * inv;
    }
    __syncthreads();

    const float* attn = S;
    for (int idx = t; idx < CC * CC; idx += blockDim.x) {
        int o = idx / CC, d = idx % CC;
        int h = d / HD, dl = d % HD;
        const float* wrow = Wp + o * CC + h * HD;
        const float* acol = attn + ((size_t)(b * HEADS + h) * HD) * HD + dl;
        float s = 0.f;
#pragma unroll
        for (int cl = 0; cl < HD; cl++)
            s += wrow[cl] * acol[(size_t)cl * HD];
        Mm[(size_t)b * CC * CC + idx] = s;
    }
}

// ---------------------------------------------------------------------------
// Launch
// ---------------------------------------------------------------------------
extern "C" void kernel_launch(void* const* d_in, const int* in_sizes, int n_in,
                              void* d_out, int out_size) {
    const float* x     = (const float*)d_in[0];
    const float* wqkv  = (const float*)d_in[1];
    const float* wdw   = (const float*)d_in[2];
    const float* wproj = (const float*)d_in[3];
    const float* temp  = (const float*)d_in[4];
    float* out = (float*)d_out;

    float *qkv_p, *S_p, *n2_p, *M_p;
    __half* qkvd_p;
    cudaGetSymbolAddress((void**)&qkv_p,  g_qkv);
    cudaGetSymbolAddress((void**)&qkvd_p, g_qkvd);
    cudaGetSymbolAddress((void**)&S_p,    g_S);
    cudaGetSymbolAddress((void**)&n2_p,   g_n2);
    cudaGetSymbolAddress((void**)&M_p,    g_M);

    // 1. zero accumulators
    {
        int nS = BB * HEADS * HD * HD;
        int nN = BB * HEADS * 2 * HD;
        zero2_kernel<<<(nS + 255) / 256, 256>>>(S_p, nS, n2_p, nN);
    }

    // 2. qkv = Wqkv @ x   (fp16 TC, fp32 accum)
    {
        dim3 grid((C3 + GBM - 1) / GBM, TN / GBN, BB);
        gemm_fp16<<<grid, 256>>>(wqkv, x, qkv_p, C3, CC,
                                 0, (size_t)CC * HW, (size_t)C3 * HW);
    }

    // 3. depthwise 3x3 -> fp16 + norms
    {
        dim3 grid(HH / 32, C3, BB);
        dwconv3h<<<grid, 256>>>(qkv_p, wdw, qkvd_p, n2_p);
    }

    // 4. Gram via MMA
    {
        dim3 grid(BB * HEADS, KSPLIT);
        gram_mma<<<grid, 256>>>(qkvd_p, S_p);
    }

    // 5. softmax + M build
    softmax_M_kernel<<<BB, 256>>>(S_p, n2_p, temp, wproj, M_p);

    // 6. out = M @ v   (fp16 TC, half B)
    {
        dim3 grid((CC + GBM - 1) / GBM, TN / GBN, BB);
        gemm_fp16h<<<grid, 256>>>(M_p, qkvd_p + (size_t)2 * CC * HW, out, CC, CC,
                                  (size_t)CC * CC, (size_t)C3 * HW, (size_t)CC * HW);
    }
}

// round 11
// speedup vs baseline: 4.0343x; 1.1816x over previous
#include <cuda_runtime.h>
#include <cuda_fp16.h>
#include <math.h>
#include <stdint.h>

// Problem constants
#define BB   16
#define CC   192
#define HH   128
#define WW   128
#define HW   16384
#define C3   576
#define HEADS 4
#define HD   48
#define TN   16384
#define KSPLIT 8

// ---------------------------------------------------------------------------
// Scratch
// ---------------------------------------------------------------------------
__device__ __half g_xh  [(size_t)BB * CC * HW];   // x in fp16
__device__ __half g_wh  [C3 * CC];                // wqkv in fp16
__device__ __half g_qkv [(size_t)BB * C3 * HW];   // qkv (pre-dwconv), fp16
__device__ __half g_qkvd[(size_t)BB * C3 * HW];   // post-dwconv, fp16
__device__ float  g_S   [BB * HEADS * HD * HD];
__device__ float  g_n2  [BB * HEADS * 2 * HD];
__device__ __half g_M   [BB * CC * CC];           // fused proj matrix, fp16

// ---------------------------------------------------------------------------
// helpers
// ---------------------------------------------------------------------------
__global__ void zero2_kernel(float* a, int na, float* b, int nb) {
    int i = blockIdx.x * blockDim.x + threadIdx.x;
    if (i < na) a[i] = 0.f;
    if (i < nb) b[i] = 0.f;
}

// fp32 -> fp16 bulk convert (8 elems/thread)
__global__ __launch_bounds__(256)
void f2h_kernel(const float* __restrict__ src, __half* __restrict__ dst, size_t n) {
    size_t i = ((size_t)blockIdx.x * blockDim.x + threadIdx.x) * 8;
    if (i + 8 <= n) {
        float4 a = *(const float4*)(src + i);
        float4 b = *(const float4*)(src + i + 4);
        __half2 h[4] = {__floats2half2_rn(a.x, a.y), __floats2half2_rn(a.z, a.w),
                        __floats2half2_rn(b.x, b.y), __floats2half2_rn(b.z, b.w)};
        *(uint4*)(dst + i) = *(uint4*)h;
    } else {
        for (; i < n; i++) dst[i] = __float2half_rn(src[i]);
    }
}

__device__ __forceinline__ void mma_f16(float* c, const unsigned* a, const unsigned* b) {
    asm volatile(
        "mma.sync.aligned.m16n8k16.row.col.f32.f16.f16.f32 "
        "{%0,%1,%2,%3}, {%4,%5,%6,%7}, {%8,%9}, {%0,%1,%2,%3};"
        : "+f"(c[0]), "+f"(c[1]), "+f"(c[2]), "+f"(c[3])
        : "r"(a[0]), "r"(a[1]), "r"(a[2]), "r"(a[3]), "r"(b[0]), "r"(b[1]));
}
__device__ __forceinline__ void ldsm_x4(unsigned* r, uint32_t addr) {
    asm volatile("ldmatrix.sync.aligned.m8n8.x4.shared.b16 {%0,%1,%2,%3}, [%4];"
                 : "=r"(r[0]), "=r"(r[1]), "=r"(r[2]), "=r"(r[3]) : "r"(addr));
}
__device__ __forceinline__ void ldsm_x2_t(unsigned* r, uint32_t addr) {
    asm volatile("ldmatrix.sync.aligned.m8n8.x2.trans.shared.b16 {%0,%1}, [%2];"
                 : "=r"(r[0]), "=r"(r[1]) : "r"(addr));
}
__device__ __forceinline__ void cpasync16(uint32_t smem, const void* g) {
    asm volatile("cp.async.ca.shared.global [%0], [%1], 16;" :: "r"(smem), "l"(g));
}
__device__ __forceinline__ void cp_commit() { asm volatile("cp.async.commit_group;"); }
template <int N>
__device__ __forceinline__ void cp_wait() { asm volatile("cp.async.wait_group %0;" :: "n"(N)); }

// ---------------------------------------------------------------------------
// fp16 TC GEMM, all-fp16 operands, cp.async mainloop.
// C[M x 16384] = A[M x K] * B[K x 16384];  C type templated (half / float).
// 128x128 tile, BK=32, 8 warps (2x4), warp tile 64x32, 2-stage pipeline.
// ---------------------------------------------------------------------------
#define GBM 128
#define GBN 128
#define GBK 32
#define APITCH 40
#define BPITCH 136

template <typename CT>
__global__ __launch_bounds__(256)
void gemm_h(const __half* __restrict__ Ag, const __half* __restrict__ Bg,
            CT* __restrict__ Cg, int M, int K,
            size_t sA, size_t sB, size_t sC) {
    __shared__ __half As[2][GBM][APITCH];
    __shared__ __half Bs[2][GBK][BPITCH];

    Ag += (size_t)blockIdx.z * sA;
    Bg += (size_t)blockIdx.z * sB;
    Cg += (size_t)blockIdx.z * sC;
    const int m0 = blockIdx.x * GBM;
    const int n0 = blockIdx.y * GBN;
    const int tid = threadIdx.x;
    const int warp = tid >> 5, lane = tid & 31;
    const int wm = (warp >> 2) * 64;
    const int wn = (warp & 3) * 32;

    float acc[4][4][4];
#pragma unroll
    for (int i = 0; i < 4; i++)
#pragma unroll
        for (int j = 0; j < 4; j++)
#pragma unroll
            for (int l = 0; l < 4; l++) acc[i][j][l] = 0.f;

    const int NK = K / GBK;

    const uint32_t aBase = (uint32_t)__cvta_generic_to_shared(&As[0][0][0]);
    const uint32_t bBase = (uint32_t)__cvta_generic_to_shared(&Bs[0][0][0]);
    const uint32_t aBufB = GBM * APITCH * 2;
    const uint32_t bBufB = GBK * BPITCH * 2;

    auto issue = [&](int it) {
        const int buf = it & 1;
        const int k0 = it * GBK;
#pragma unroll
        for (int i = 0; i < 2; i++) {
            int idx = tid * 2 + i;                 // A: 512 x 16B (128 rows x 4 segs)
            int row = idx >> 2, seg = idx & 3;
            int r = m0 + row; if (r >= M) r = M - 1;
            cpasync16(aBase + buf * aBufB + (row * APITCH + seg * 8) * 2,
                      Ag + (size_t)r * K + k0 + seg * 8);
        }
#pragma unroll
        for (int i = 0; i < 2; i++) {
            int idx = tid * 2 + i;                 // B: 512 x 16B (32 k x 16 segs)
            int k = idx >> 4, seg = idx & 15;
            cpasync16(bBase + buf * bBufB + (k * BPITCH + seg * 8) * 2,
                      Bg + (size_t)(k0 + k) * TN + n0 + seg * 8);
        }
        cp_commit();
    };

    issue(0);

    const int arow = wm + (lane & 15);
    const int acolh = (lane >> 4) << 3;
    const int brow = lane & 15;

    for (int it = 0; it < NK; it++) {
        if (it + 1 < NK) { issue(it + 1); cp_wait<1>(); }
        else             { cp_wait<0>(); }
        __syncthreads();

        const int buf = it & 1;
        const uint32_t aB = aBase + buf * aBufB;
        const uint32_t bB = bBase + buf * bBufB;
#pragma unroll
        for (int ks = 0; ks < GBK; ks += 16) {
            unsigned af[4][4];
#pragma unroll
            for (int mt = 0; mt < 4; mt++)
                ldsm_x4(af[mt], aB + ((arow + mt * 16) * APITCH + ks + acolh) * 2);
            unsigned bf[4][2];
#pragma unroll
            for (int nt = 0; nt < 4; nt++)
                ldsm_x2_t(bf[nt], bB + ((ks + brow) * BPITCH + wn + nt * 8) * 2);
#pragma unroll
            for (int mt = 0; mt < 4; mt++)
#pragma unroll
                for (int nt = 0; nt < 4; nt++)
                    mma_f16(acc[mt][nt], af[mt], bf[nt]);
        }
        __syncthreads();
    }

    // epilogue
    const int frow = lane >> 2;
    const int qc = (lane & 3) * 2;
#pragma unroll
    for (int mt = 0; mt < 4; mt++) {
        int gr = m0 + wm + mt * 16 + frow;
#pragma unroll
        for (int nt = 0; nt < 4; nt++) {
            int gc = n0 + wn + nt * 8 + qc;
            if (sizeof(CT) == 2) {
                if (gr < M)
                    *(__half2*)((__half*)Cg + (size_t)gr * TN + gc) =
                        __floats2half2_rn(acc[mt][nt][0], acc[mt][nt][1]);
                if (gr + 8 < M)
                    *(__half2*)((__half*)Cg + (size_t)(gr + 8) * TN + gc) =
                        __floats2half2_rn(acc[mt][nt][2], acc[mt][nt][3]);
            } else {
                if (gr < M)
                    *(float2*)((float*)Cg + (size_t)gr * TN + gc) =
                        make_float2(acc[mt][nt][0], acc[mt][nt][1]);
                if (gr + 8 < M)
                    *(float2*)((float*)Cg + (size_t)(gr + 8) * TN + gc) =
                        make_float2(acc[mt][nt][2], acc[mt][nt][3]);
            }
        }
    }
}

// ---------------------------------------------------------------------------
// Depthwise 3x3: fp16 in -> fp16 out + fp32 norms of rounded values
// ---------------------------------------------------------------------------
__global__ __launch_bounds__(256)
void dwconv_h(const __half* __restrict__ in, const float* __restrict__ wdw,
              __half* __restrict__ out, float* __restrict__ norm2) {
    const int y0 = blockIdx.x * 32;
    const int ch = blockIdx.y;
    const int b  = blockIdx.z;
    const __half* base = in + ((size_t)b * C3 + ch) * HW;
    __half* obase = out + ((size_t)b * C3 + ch) * HW;

    __shared__ float t[34][136];

    if (threadIdx.x < 34) {
        t[threadIdx.x][3]   = 0.f;
        t[threadIdx.x][132] = 0.f;
    }
    for (int i = threadIdx.x; i < 34 * 32; i += 256) {
        int r = i >> 5, j = i & 31;
        int gy = y0 - 1 + r;
        float4 v = make_float4(0.f, 0.f, 0.f, 0.f);
        if (gy >= 0 && gy < HH) {
            uint2 u = *(const uint2*)(base + gy * WW + 4 * j);
            __half2 h0 = *(__half2*)&u.x;
            __half2 h1 = *(__half2*)&u.y;
            v = make_float4(__low2float(h0), __high2float(h0),
                            __low2float(h1), __high2float(h1));
        }
        *(float4*)&t[r][4 + 4 * j] = v;
    }
    __syncthreads();

    float w[9];
#pragma unroll
    for (int i = 0; i < 9; i++) w[i] = wdw[ch * 9 + i];

    const int ry = threadIdx.x >> 5;
    const int x0 = (threadIdx.x & 31) << 2;
    const int c  = 4 + x0;

    float ss = 0.f;
#pragma unroll
    for (int jj = 0; jj < 4; jj++) {
        int y = ry * 4 + jj;
        float4 o = make_float4(0.f, 0.f, 0.f, 0.f);
#pragma unroll
        for (int dy = 0; dy < 3; dy++) {
            const float* rr = t[y + dy];
            float4 v = *(const float4*)&rr[c];
            float  l = rr[c - 1];
            float  rg = rr[c + 4];
            float w0 = w[dy * 3 + 0], w1 = w[dy * 3 + 1], w2 = w[dy * 3 + 2];
            o.x += l   * w0 + v.x * w1 + v.y * w2;
            o.y += v.x * w0 + v.y * w1 + v.z * w2;
            o.z += v.y * w0 + v.z * w1 + v.w * w2;
            o.w += v.z * w0 + v.w * w1 + rg  * w2;
        }
        __half2 h01 = __floats2half2_rn(o.x, o.y);
        __half2 h23 = __floats2half2_rn(o.z, o.w);
        *(__half2*)(obase + (y0 + y) * WW + x0)     = h01;
        *(__half2*)(obase + (y0 + y) * WW + x0 + 2) = h23;
        float r0 = __low2float(h01), r1 = __high2float(h01);
        float r2 = __low2float(h23), r3 = __high2float(h23);
        ss += r0 * r0 + r1 * r1 + r2 * r2 + r3 * r3;
    }

    if (ch < 2 * CC) {
#pragma unroll
        for (int off = 16; off > 0; off >>= 1)
            ss += __shfl_down_sync(0xffffffffu, ss, off);
        __shared__ float wsum[8];
        if ((threadIdx.x & 31) == 0) wsum[threadIdx.x >> 5] = ss;
        __syncthreads();
        if (threadIdx.x == 0) {
            float tsum = 0.f;
#pragma unroll
            for (int i = 0; i < 8; i++) tsum += wsum[i];
            int idx;
            if (ch < CC) idx = (b * HEADS + ch / HD) * (2 * HD) + (ch % HD);
            else { int c2 = ch - CC; idx = (b * HEADS + c2 / HD) * (2 * HD) + HD + (c2 % HD); }
            atomicAdd(&norm2[idx], tsum);
        }
    }
}

// ---------------------------------------------------------------------------
// Gram via fp16 MMA, fragments direct from gmem (unchanged from R10)
// ---------------------------------------------------------------------------
__global__ __launch_bounds__(256)
void gram_mma(const __half* __restrict__ qkvd, float* __restrict__ S) {
    const int bh = blockIdx.x;
    const int b = bh / HEADS, h = bh % HEADS;
    const __half* Q  = qkvd + ((size_t)b * C3 + h * HD) * HW;
    const __half* Kp = qkvd + ((size_t)b * C3 + CC + h * HD) * HW;

    __shared__ float Ssh[HD * HD];
    for (int i = threadIdx.x; i < HD * HD; i += 256) Ssh[i] = 0.f;
    __syncthreads();

    const int warp = threadIdx.x >> 5, lane = threadIdx.x & 31;
    const int g  = lane >> 2;
    const int cq = (lane & 3) << 1;

    const int span = HW / (KSPLIT * 8);
    const int pc0 = (blockIdx.y * 8 + warp) * span;

    float acc[3][6][4];
#pragma unroll
    for (int i = 0; i < 3; i++)
#pragma unroll
        for (int j = 0; j < 6; j++)
#pragma unroll
            for (int l = 0; l < 4; l++) acc[i][j][l] = 0.f;

    for (int pc = pc0; pc < pc0 + span; pc += 16) {
        unsigned af[3][4], bf[6][2];
#pragma unroll
        for (int mt = 0; mt < 3; mt++) {
            const __half* qr = Q + (size_t)(mt * 16 + g) * HW + pc + cq;
            af[mt][0] = *(const unsigned*)(qr);
            af[mt][1] = *(const unsigned*)(qr + 8 * HW);
            af[mt][2] = *(const unsigned*)(qr + 8);
            af[mt][3] = *(const unsigned*)(qr + 8 * HW + 8);
        }
#pragma unroll
        for (int nt = 0; nt < 6; nt++) {
            const __half* kr = Kp + (size_t)(nt * 8 + g) * HW + pc + cq;
            bf[nt][0] = *(const unsigned*)(kr);
            bf[nt][1] = *(const unsigned*)(kr + 8);
        }
#pragma unroll
        for (int mt = 0; mt < 3; mt++)
#pragma unroll
            for (int nt = 0; nt < 6; nt++)
                mma_f16(acc[mt][nt], af[mt], bf[nt]);
    }

#pragma unroll
    for (int mt = 0; mt < 3; mt++) {
#pragma unroll
        for (int nt = 0; nt < 6; nt++) {
            int r0 = mt * 16 + g;
            int c0 = nt * 8 + cq;
            atomicAdd(&Ssh[r0 * HD + c0],           acc[mt][nt][0]);
            atomicAdd(&Ssh[r0 * HD + c0 + 1],       acc[mt][nt][1]);
            atomicAdd(&Ssh[(r0 + 8) * HD + c0],     acc[mt][nt][2]);
            atomicAdd(&Ssh[(r0 + 8) * HD + c0 + 1], acc[mt][nt][3]);
        }
    }
    __syncthreads();

    float* Sg = S + (size_t)bh * HD * HD;
    for (int i = threadIdx.x; i < HD * HD; i += 256)
        atomicAdd(&Sg[i], Ssh[i]);
}

// ---------------------------------------------------------------------------
// Softmax (48) + M = Wproj @ blockdiag(attn) -> fp16, one block per batch
// ---------------------------------------------------------------------------
__global__ __launch_bounds__(256)
void softmax_M_kernel(float* __restrict__ S, const float* __restrict__ norm2,
                      const float* __restrict__ temperature,
                      const float* __restrict__ Wp, __half* __restrict__ Mm) {
    const int b = blockIdx.x;
    const int t = threadIdx.x;

    if (t < HEADS * HD) {
        int h = t / HD, i = t % HD;
        int bh = b * HEADS + h;
        const float* n2 = norm2 + bh * (2 * HD);
        float nq = fmaxf(sqrtf(n2[i]), 1e-12f);
        float tv = temperature[h];
        float* Srow = S + ((size_t)bh * HD + i) * HD;

        float row[48];
        float mx = -1e30f;
#pragma unroll
        for (int j = 0; j < HD; j++) {
            float nk = fmaxf(sqrtf(n2[HD + j]), 1e-12f);
            row[j] = Srow[j] / (nq * nk) * tv;
            mx = fmaxf(mx, row[j]);
        }
        float sum = 0.f;
#pragma unroll
        for (int j = 0; j < HD; j++) {
            row[j] = expf(row[j] - mx);
            sum += row[j];
        }
        float inv = 1.f / sum;
#pragma unroll
        for (int j = 0; j < HD; j++) Srow[j] = row[j] * inv;
    }
    __syncthreads();

    const float* attn = S;
    for (int idx = t; idx < CC * CC; idx += blockDim.x) {
        int o = idx / CC, d = idx % CC;
        int h = d / HD, dl = d % HD;
        const float* wrow = Wp + o * CC + h * HD;
        const float* acol = attn + ((size_t)(b * HEADS + h) * HD) * HD + dl;
        float s = 0.f;
#pragma unroll
        for (int cl = 0; cl < HD; cl++)
            s += wrow[cl] * acol[(size_t)cl * HD];
        Mm[(size_t)b * CC * CC + idx] = __float2half_rn(s);
    }
}

// ---------------------------------------------------------------------------
// Launch
// ---------------------------------------------------------------------------
extern "C" void kernel_launch(void* const* d_in, const int* in_sizes, int n_in,
                              void* d_out, int out_size) {
    const float* x     = (const float*)d_in[0];
    const float* wqkv  = (const float*)d_in[1];
    const float* wdw   = (const float*)d_in[2];
    const float* wproj = (const float*)d_in[3];
    const float* temp  = (const float*)d_in[4];
    float* out = (float*)d_out;

    __half *xh_p, *wh_p, *qkv_p, *qkvd_p, *M_p;
    float *S_p, *n2_p;
    cudaGetSymbolAddress((void**)&xh_p,   g_xh);
    cudaGetSymbolAddress((void**)&wh_p,   g_wh);
    cudaGetSymbolAddress((void**)&qkv_p,  g_qkv);
    cudaGetSymbolAddress((void**)&qkvd_p, g_qkvd);
    cudaGetSymbolAddress((void**)&S_p,    g_S);
    cudaGetSymbolAddress((void**)&n2_p,   g_n2);
    cudaGetSymbolAddress((void**)&M_p,    g_M);

    // 1. zero accumulators + fp16 conversions
    {
        int nS = BB * HEADS * HD * HD;
        int nN = BB * HEADS * 2 * HD;
        zero2_kernel<<<(nS + 255) / 256, 256>>>(S_p, nS, n2_p, nN);
        size_t nx = (size_t)BB * CC * HW;
        f2h_kernel<<<(unsigned)((nx / 8 + 255) / 256), 256>>>(x, xh_p, nx);
        size_t nw = (size_t)C3 * CC;
        f2h_kernel<<<(unsigned)((nw / 8 + 255) / 256), 256>>>(wqkv, wh_p, nw);
    }

    // 2. qkv = Wqkv @ x   (all-fp16 cp.async GEMM, fp16 out)
    {
        dim3 grid((C3 + GBM - 1) / GBM, TN / GBN, BB);
        gemm_h<__half><<<grid, 256>>>(wh_p, xh_p, qkv_p, C3, CC,
                                      0, (size_t)CC * HW, (size_t)C3 * HW);
    }

    // 3. depthwise 3x3 (fp16 in/out) + norms
    {
        dim3 grid(HH / 32, C3, BB);
        dwconv_h<<<grid, 256>>>(qkv_p, wdw, qkvd_p, n2_p);
    }

    // 4. Gram via MMA
    {
        dim3 grid(BB * HEADS, KSPLIT);
        gram_mma<<<grid, 256>>>(qkvd_p, S_p);
    }

    // 5. softmax + M build (fp16 M)
    softmax_M_kernel<<<BB, 256>>>(S_p, n2_p, temp, wproj, M_p);

    // 6. out = M @ v   (all-fp16 cp.async GEMM, fp32 out)
    {
        dim3 grid((CC + GBM - 1) / GBM, TN / GBN, BB);
        gemm_h<float><<<grid, 256>>>(M_p, qkvd_p + (size_t)2 * CC * HW, out, CC, CC,
                                     (size_t)CC * CC, (size_t)C3 * HW, (size_t)CC * HW);
    }
}